// round 1
// baseline (speedup 1.0000x reference)
#include <cuda_runtime.h>
#include <cuda_bf16.h>
#include <math.h>

// Problem constants
#define B 4
#define L 2048
#define S 2048
#define D 1024
#define H 16
#define DH 64

// ---------------------------------------------------------------------------
// Scratch (device globals — no allocation allowed)
// ---------------------------------------------------------------------------
__device__ float g_q[B * L * D];
__device__ float g_k[B * S * D];
__device__ float g_v[B * S * D];
__device__ float g_ao[B * L * D];

// ---------------------------------------------------------------------------
// SGEMM: Y[n, m] = sum_k X[n,k] * W[m,k]   (i.e. Y = X @ W^T)
// X: [Nrows, K] row-major, W: [Mcols, K] row-major.
// 128x128 tile, BK=8, 256 threads, 8x8 per thread.
// ---------------------------------------------------------------------------
#define GB_M 128
#define GB_N 128
#define GB_K 8

__global__ __launch_bounds__(256, 2)
void gemm_nt_kernel(const float* __restrict__ X, const float* __restrict__ W,
                    float* __restrict__ Y, int Nrows, int K, int Mcols)
{
    __shared__ float As[GB_K][GB_M];
    __shared__ float Bs[GB_K][GB_N];

    const int tid = threadIdx.x;
    const int tx = tid & 15;       // 0..15 -> N (output col) direction
    const int ty = tid >> 4;       // 0..15 -> M (row) direction

    const float* Xb = X + (size_t)blockIdx.y * GB_M * K;
    const float* Wb = W + (size_t)blockIdx.x * GB_N * K;

    float acc[8][8];
#pragma unroll
    for (int i = 0; i < 8; i++)
#pragma unroll
        for (int j = 0; j < 8; j++) acc[i][j] = 0.f;

    const int lrow = tid >> 1;           // 0..127
    const int lcol = (tid & 1) * 4;      // 0 or 4

    for (int k0 = 0; k0 < K; k0 += GB_K) {
        float4 xa = *reinterpret_cast<const float4*>(Xb + (size_t)lrow * K + k0 + lcol);
        float4 wa = *reinterpret_cast<const float4*>(Wb + (size_t)lrow * K + k0 + lcol);
        __syncthreads();   // protect previous iteration's reads
        As[lcol + 0][lrow] = xa.x; As[lcol + 1][lrow] = xa.y;
        As[lcol + 2][lrow] = xa.z; As[lcol + 3][lrow] = xa.w;
        Bs[lcol + 0][lrow] = wa.x; Bs[lcol + 1][lrow] = wa.y;
        Bs[lcol + 2][lrow] = wa.z; Bs[lcol + 3][lrow] = wa.w;
        __syncthreads();

#pragma unroll
        for (int kk = 0; kk < GB_K; kk++) {
            const float4* a4 = reinterpret_cast<const float4*>(&As[kk][ty * 8]);
            const float4* b4 = reinterpret_cast<const float4*>(&Bs[kk][tx * 8]);
            float4 a0 = a4[0], a1 = a4[1];
            float4 b0 = b4[0], b1 = b4[1];
            float a[8] = {a0.x, a0.y, a0.z, a0.w, a1.x, a1.y, a1.z, a1.w};
            float b[8] = {b0.x, b0.y, b0.z, b0.w, b1.x, b1.y, b1.z, b1.w};
#pragma unroll
            for (int i = 0; i < 8; i++)
#pragma unroll
                for (int j = 0; j < 8; j++)
                    acc[i][j] = fmaf(a[i], b[j], acc[i][j]);
        }
    }

    const int row0 = blockIdx.y * GB_M + ty * 8;
    const int col0 = blockIdx.x * GB_N + tx * 8;
#pragma unroll
    for (int i = 0; i < 8; i++) {
        float4 v0 = make_float4(acc[i][0], acc[i][1], acc[i][2], acc[i][3]);
        float4 v1 = make_float4(acc[i][4], acc[i][5], acc[i][6], acc[i][7]);
        *reinterpret_cast<float4*>(Y + (size_t)(row0 + i) * Mcols + col0)     = v0;
        *reinterpret_cast<float4*>(Y + (size_t)(row0 + i) * Mcols + col0 + 4) = v1;
    }
}

// ---------------------------------------------------------------------------
// Flash attention (fp32, causal). 64x64 tiles, dh=64, 256 threads.
// Per block: (b, h, m-tile of 64 queries). Online softmax.
// Dynamic smem layout (pitch 65 to avoid bank conflicts):
//   Qs[64][65], Ks[64][65], Vs[64][65], Ps[64][65], red[64][16],
//   rmax[64], rsum[64], rfac[64]
// ---------------------------------------------------------------------------
#define TP 65
#define FA_TILE 64

__global__ __launch_bounds__(256)
void flash_attn_kernel(const float* __restrict__ Q, const float* __restrict__ Kg,
                       const float* __restrict__ Vg, float* __restrict__ O)
{
    extern __shared__ float sm[];
    float* Qs   = sm;                       // 64*65
    float* Ks   = Qs + FA_TILE * TP;        // 64*65
    float* Vs   = Ks + FA_TILE * TP;        // 64*65
    float* Ps   = Vs + FA_TILE * TP;        // 64*65
    float* red  = Ps + FA_TILE * TP;        // 64*16
    float* rmax = red + FA_TILE * 16;       // 64
    float* rsum = rmax + FA_TILE;           // 64
    float* rfac = rsum + FA_TILE;           // 64

    const int tid = threadIdx.x;
    const int tx = tid & 15;    // 0..15
    const int ty = tid >> 4;    // 0..15
    const int mtile = blockIdx.x;          // 0..L/64-1
    const int bh = blockIdx.y;             // 0..B*H-1
    const int b = bh / H;
    const int h = bh % H;
    const int m0 = mtile * FA_TILE;

    const float* Qbase = Q  + (size_t)b * L * D + h * DH;
    const float* Kbase = Kg + (size_t)b * S * D + h * DH;
    const float* Vbase = Vg + (size_t)b * S * D + h * DH;

    const float scale = 0.125f;   // 1/sqrt(64)

    // Load Q tile (scaled)
    for (int idx = tid; idx < FA_TILE * DH; idx += 256) {
        int r = idx >> 6, c = idx & 63;
        Qs[r * TP + c] = Qbase[(size_t)(m0 + r) * D + c] * scale;
    }
    if (tid < 64) { rmax[tid] = -INFINITY; rsum[tid] = 0.f; }

    float Oacc[4][4];
#pragma unroll
    for (int i = 0; i < 4; i++)
#pragma unroll
        for (int j = 0; j < 4; j++) Oacc[i][j] = 0.f;

    __syncthreads();

    for (int jt = 0; jt <= mtile; jt++) {
        const int n0 = jt * FA_TILE;

        // Load K and V tiles
        for (int idx = tid; idx < FA_TILE * DH; idx += 256) {
            int r = idx >> 6, c = idx & 63;
            Ks[r * TP + c] = Kbase[(size_t)(n0 + r) * D + c];
            Vs[r * TP + c] = Vbase[(size_t)(n0 + r) * D + c];
        }
        __syncthreads();

        // S tile: thread owns rows m=ty*4+i, cols n=tx*4+j
        float s[4][4];
#pragma unroll
        for (int i = 0; i < 4; i++)
#pragma unroll
            for (int j = 0; j < 4; j++) s[i][j] = 0.f;

#pragma unroll 16
        for (int d = 0; d < DH; d++) {
            float a[4], bb[4];
#pragma unroll
            for (int i = 0; i < 4; i++) a[i]  = Qs[(ty * 4 + i) * TP + d];
#pragma unroll
            for (int j = 0; j < 4; j++) bb[j] = Ks[(tx * 4 + j) * TP + d];
#pragma unroll
            for (int i = 0; i < 4; i++)
#pragma unroll
                for (int j = 0; j < 4; j++)
                    s[i][j] = fmaf(a[i], bb[j], s[i][j]);
        }

        // Causal mask on diagonal tile
        if (jt == mtile) {
#pragma unroll
            for (int i = 0; i < 4; i++)
#pragma unroll
                for (int j = 0; j < 4; j++)
                    if (tx * 4 + j > ty * 4 + i) s[i][j] = -INFINITY;
        }

        // Partial row max
#pragma unroll
        for (int i = 0; i < 4; i++) {
            float mx = fmaxf(fmaxf(s[i][0], s[i][1]), fmaxf(s[i][2], s[i][3]));
            red[(ty * 4 + i) * 16 + tx] = mx;
        }
        __syncthreads();   // (A)

        if (tid < 64) {
            float mx = red[tid * 16];
#pragma unroll
            for (int q = 1; q < 16; q++) mx = fmaxf(mx, red[tid * 16 + q]);
            float old = rmax[tid];
            float nm  = fmaxf(old, mx);
            rmax[tid] = nm;
            rfac[tid] = (old == -INFINITY) ? 0.f : __expf(old - nm);
        }
        __syncthreads();   // (B)

        // P = exp(s - rowmax); store to smem; partial sums; rescale Oacc
#pragma unroll
        for (int i = 0; i < 4; i++) {
            float nm = rmax[ty * 4 + i];
            float f  = rfac[ty * 4 + i];
            float psum = 0.f;
#pragma unroll
            for (int j = 0; j < 4; j++) {
                float p = __expf(s[i][j] - nm);   // exp(-inf) -> 0
                Ps[(ty * 4 + i) * TP + tx * 4 + j] = p;
                psum += p;
                Oacc[i][j] *= f;
            }
            red[(ty * 4 + i) * 16 + tx] = psum;
        }
        __syncthreads();   // (C)

        if (tid < 64) {
            float sum = 0.f;
#pragma unroll
            for (int q = 0; q < 16; q++) sum += red[tid * 16 + q];
            rsum[tid] = rsum[tid] * rfac[tid] + sum;
        }

        // O += P @ V : thread owns rows m=ty*4+i, dh cols d=tx*4+j
#pragma unroll 16
        for (int n = 0; n < FA_TILE; n++) {
            float p[4], vv[4];
#pragma unroll
            for (int i = 0; i < 4; i++) p[i]  = Ps[(ty * 4 + i) * TP + n];
#pragma unroll
            for (int j = 0; j < 4; j++) vv[j] = Vs[n * TP + tx * 4 + j];
#pragma unroll
            for (int i = 0; i < 4; i++)
#pragma unroll
                for (int j = 0; j < 4; j++)
                    Oacc[i][j] = fmaf(p[i], vv[j], Oacc[i][j]);
        }
        __syncthreads();   // (D) protect Ks/Vs/red/rfac for next iteration
    }

    // Epilogue: normalize and write [B, L, H*DH]
    float* Obase = O + ((size_t)b * L + m0) * D + h * DH;
#pragma unroll
    for (int i = 0; i < 4; i++) {
        int m = ty * 4 + i;
        float inv = 1.f / rsum[m];
#pragma unroll
        for (int j = 0; j < 4; j++)
            Obase[(size_t)m * D + tx * 4 + j] = Oacc[i][j] * inv;
    }
}

// ---------------------------------------------------------------------------
// Launch
// ---------------------------------------------------------------------------
extern "C" void kernel_launch(void* const* d_in, const int* in_sizes, int n_in,
                              void* d_out, int out_size)
{
    const float* q_in = (const float*)d_in[0];
    const float* k_in = (const float*)d_in[1];
    const float* v_in = (const float*)d_in[2];
    const float* Wq   = (const float*)d_in[3];
    const float* Wk   = (const float*)d_in[4];
    const float* Wv   = (const float*)d_in[5];
    const float* Wo   = (const float*)d_in[6];
    float* out = (float*)d_out;

    float *gq, *gk, *gv, *gao;
    cudaGetSymbolAddress((void**)&gq,  g_q);
    cudaGetSymbolAddress((void**)&gk,  g_k);
    cudaGetSymbolAddress((void**)&gv,  g_v);
    cudaGetSymbolAddress((void**)&gao, g_ao);

    const int Nrows = B * L;   // 8192
    dim3 gemm_grid(D / GB_N, Nrows / GB_M);   // (8, 64)
    dim3 gemm_blk(256);

    gemm_nt_kernel<<<gemm_grid, gemm_blk>>>(q_in, Wq, gq, Nrows, D, D);
    gemm_nt_kernel<<<gemm_grid, gemm_blk>>>(k_in, Wk, gk, Nrows, D, D);
    gemm_nt_kernel<<<gemm_grid, gemm_blk>>>(v_in, Wv, gv, Nrows, D, D);

    // Flash attention
    const int smem_bytes = (4 * FA_TILE * TP + FA_TILE * 16 + 3 * FA_TILE) * sizeof(float);
    cudaFuncSetAttribute(flash_attn_kernel,
                         cudaFuncAttributeMaxDynamicSharedMemorySize, smem_bytes);
    dim3 fa_grid(L / FA_TILE, B * H);   // (32, 64)
    flash_attn_kernel<<<fa_grid, 256, smem_bytes>>>(gq, gk, gv, gao);

    // Output projection
    gemm_nt_kernel<<<gemm_grid, gemm_blk>>>(gao, Wo, out, Nrows, D, D);
}

// round 4
// speedup vs baseline: 1.4986x; 1.4986x over previous
#include <cuda_runtime.h>
#include <cuda_bf16.h>
#include <math.h>
#include <stdint.h>

// Problem constants
#define B 4
#define L 2048
#define S 2048
#define D 1024
#define H 16
#define DH 64

// ---------------------------------------------------------------------------
// Scratch (device globals — no allocation allowed)
// ---------------------------------------------------------------------------
__device__ float g_q[B * L * D];
__device__ float g_k[B * S * D];
__device__ float g_v[B * S * D];
__device__ float g_ao[B * L * D];

// bf16 split buffers
__device__ __nv_bfloat16 g_a_hi[B * L * D];
__device__ __nv_bfloat16 g_a_lo[B * L * D];
__device__ __nv_bfloat16 g_b_hi[B * L * D];
__device__ __nv_bfloat16 g_b_lo[B * L * D];
__device__ __nv_bfloat16 g_c_hi[B * L * D];
__device__ __nv_bfloat16 g_c_lo[B * L * D];
__device__ __nv_bfloat16 g_wq_hi[D * D];
__device__ __nv_bfloat16 g_wq_lo[D * D];
__device__ __nv_bfloat16 g_wk_hi[D * D];
__device__ __nv_bfloat16 g_wk_lo[D * D];
__device__ __nv_bfloat16 g_wv_hi[D * D];
__device__ __nv_bfloat16 g_wv_lo[D * D];
__device__ __nv_bfloat16 g_wo_hi[D * D];
__device__ __nv_bfloat16 g_wo_lo[D * D];

// ---------------------------------------------------------------------------
// Helpers (baseline compute_103-safe PTX only: cp.async, ldmatrix, mma.sync)
// ---------------------------------------------------------------------------
__device__ __forceinline__ uint32_t smem_u32(const void* p) {
    uint32_t a;
    asm("{ .reg .u64 t; cvta.to.shared.u64 t, %1; cvt.u32.u64 %0, t; }"
        : "=r"(a) : "l"(p));
    return a;
}

#define CP16(dst, src) \
    asm volatile("cp.async.cg.shared.global [%0], [%1], 16;" \
        :: "r"(dst), "l"(src) : "memory")

#define CP_COMMIT() asm volatile("cp.async.commit_group;" ::: "memory")
#define CP_WAIT1()  asm volatile("cp.async.wait_group 1;" ::: "memory")
#define CP_WAIT0()  asm volatile("cp.async.wait_group 0;" ::: "memory")

#define LDSM_X4(r0, r1, r2, r3, addr) \
    asm volatile("ldmatrix.sync.aligned.m8n8.x4.shared.b16 {%0,%1,%2,%3}, [%4];" \
        : "=r"(r0), "=r"(r1), "=r"(r2), "=r"(r3) : "r"(addr))

#define MMA_BF16(c, a, b0, b1) \
    asm volatile("mma.sync.aligned.m16n8k16.row.col.f32.bf16.bf16.f32 " \
        "{%0,%1,%2,%3}, {%4,%5,%6,%7}, {%8,%9}, {%0,%1,%2,%3};" \
        : "+f"((c)[0]), "+f"((c)[1]), "+f"((c)[2]), "+f"((c)[3]) \
        : "r"((a)[0]), "r"((a)[1]), "r"((a)[2]), "r"((a)[3]), \
          "r"(b0), "r"(b1))

// ---------------------------------------------------------------------------
// fp32 -> (bf16 hi, bf16 lo) split kernel.
// ---------------------------------------------------------------------------
__global__ __launch_bounds__(256)
void split_bf16_kernel(const float* __restrict__ x,
                       __nv_bfloat16* __restrict__ hi,
                       __nv_bfloat16* __restrict__ lo, int n4)
{
    int i = blockIdx.x * blockDim.x + threadIdx.x;
    if (i >= n4) return;
    float4 v = reinterpret_cast<const float4*>(x)[i];
    __nv_bfloat16 h0 = __float2bfloat16(v.x);
    __nv_bfloat16 h1 = __float2bfloat16(v.y);
    __nv_bfloat16 h2 = __float2bfloat16(v.z);
    __nv_bfloat16 h3 = __float2bfloat16(v.w);
    __nv_bfloat16 l0 = __float2bfloat16(v.x - __bfloat162float(h0));
    __nv_bfloat16 l1 = __float2bfloat16(v.y - __bfloat162float(h1));
    __nv_bfloat16 l2 = __float2bfloat16(v.z - __bfloat162float(h2));
    __nv_bfloat16 l3 = __float2bfloat16(v.w - __bfloat162float(h3));
    __nv_bfloat162 hp0(h0, h1), hp1(h2, h3), lp0(l0, l1), lp1(l2, l3);
    uint2 hv, lv;
    hv.x = *reinterpret_cast<uint32_t*>(&hp0);
    hv.y = *reinterpret_cast<uint32_t*>(&hp1);
    lv.x = *reinterpret_cast<uint32_t*>(&lp0);
    lv.y = *reinterpret_cast<uint32_t*>(&lp1);
    reinterpret_cast<uint2*>(hi)[i] = hv;
    reinterpret_cast<uint2*>(lo)[i] = lv;
}

// ---------------------------------------------------------------------------
// HMMA split-bf16 GEMM:  Y[m, n] = sum_k A[m,k] * W[n,k]  (fp32 out)
// CTA tile 128x128, warp tile 64x32 (8 warps as 2x4), k-chunk 32, 2 stages.
// SMEM tiles are 128 rows x 64B with 80B pitch (conflict-free for ldmatrix).
// ---------------------------------------------------------------------------
#define KDIM 1024
#define NCH 32                 // 1024 / 32
#define PITCH 80
#define TSZ (128 * PITCH)      // 10240 B per tile
#define STAGE_B (4 * TSZ)      // Ahi, Alo, Bhi, Blo
#define GEMM_SMEM (2 * STAGE_B)  // 81920 B

__global__ __launch_bounds__(256, 1)
void gemm_mma_kernel(const __nv_bfloat16* __restrict__ Ahi,
                     const __nv_bfloat16* __restrict__ Alo,
                     const __nv_bfloat16* __restrict__ Whi,
                     const __nv_bfloat16* __restrict__ Wlo,
                     float* __restrict__ Y)
{
    extern __shared__ char smem[];
    const uint32_t sb = smem_u32(smem);
    const int tid = threadIdx.x;
    const int lane = tid & 31;
    const int wid = tid >> 5;
    const int warp_m = wid >> 2;     // 0..1
    const int warp_n = wid & 3;      // 0..3
    const int m0 = blockIdx.y * 128;
    const int n0 = blockIdx.x * 128;

    float acc[4][4][4];
#pragma unroll
    for (int a = 0; a < 4; a++)
#pragma unroll
        for (int b = 0; b < 4; b++)
#pragma unroll
            for (int c = 0; c < 4; c++) acc[a][b][c] = 0.f;

    auto prefetch = [&](int c, int stage) {
        const uint32_t sbase = sb + stage * STAGE_B;
        const int k0 = c * 32;
#pragma unroll
        for (int j = 0; j < 2; j++) {
            const int idx = j * 256 + tid;
            const int r  = (idx & 7) + (idx >> 5) * 8;   // 0..127
            const int ch = (idx >> 3) & 3;               // 16B chunk
            const uint32_t so = (uint32_t)(r * PITCH + ch * 16);
            const char* ga_hi = (const char*)(Ahi + (size_t)(m0 + r) * KDIM + k0) + ch * 16;
            const char* ga_lo = (const char*)(Alo + (size_t)(m0 + r) * KDIM + k0) + ch * 16;
            const char* gb_hi = (const char*)(Whi + (size_t)(n0 + r) * KDIM + k0) + ch * 16;
            const char* gb_lo = (const char*)(Wlo + (size_t)(n0 + r) * KDIM + k0) + ch * 16;
            CP16(sbase + so,               ga_hi);
            CP16(sbase + TSZ + so,         ga_lo);
            CP16(sbase + 2 * TSZ + so,     gb_hi);
            CP16(sbase + 3 * TSZ + so,     gb_lo);
        }
    };

    prefetch(0, 0); CP_COMMIT();
    prefetch(1, 1); CP_COMMIT();

    for (int c = 0; c < NCH; c++) {
        const int stage = c & 1;
        CP_WAIT1();
        __syncthreads();
        const uint32_t sbase = sb + stage * STAGE_B;

#pragma unroll
        for (int s = 0; s < 2; s++) {     // two k16 steps per 32-chunk
            uint32_t ah[4][4], al[4][4], bh[4][2], bl[4][2];
            const int lr = lane & 15;
            const int lh = lane >> 4;
#pragma unroll
            for (int mt = 0; mt < 4; mt++) {
                const uint32_t ad = sbase +
                    (uint32_t)((warp_m * 64 + mt * 16 + lr) * PITCH + s * 32 + lh * 16);
                LDSM_X4(ah[mt][0], ah[mt][1], ah[mt][2], ah[mt][3], ad);
                LDSM_X4(al[mt][0], al[mt][1], al[mt][2], al[mt][3], ad + TSZ);
            }
            const int br = (lane & 7) + ((lane >> 4) & 1) * 8;
            const int bk = ((lane >> 3) & 1) * 16;
#pragma unroll
            for (int np = 0; np < 2; np++) {
                const uint32_t bd = sbase + 2 * TSZ +
                    (uint32_t)((warp_n * 32 + np * 16 + br) * PITCH + s * 32 + bk);
                uint32_t t0, t1, t2, t3;
                LDSM_X4(t0, t1, t2, t3, bd);
                bh[np * 2][0] = t0; bh[np * 2][1] = t1;
                bh[np * 2 + 1][0] = t2; bh[np * 2 + 1][1] = t3;
                LDSM_X4(t0, t1, t2, t3, bd + TSZ);
                bl[np * 2][0] = t0; bl[np * 2][1] = t1;
                bl[np * 2 + 1][0] = t2; bl[np * 2 + 1][1] = t3;
            }
#pragma unroll
            for (int mt = 0; mt < 4; mt++) {
#pragma unroll
                for (int nt = 0; nt < 4; nt++) {
                    MMA_BF16(acc[mt][nt], ah[mt], bh[nt][0], bh[nt][1]);
                    MMA_BF16(acc[mt][nt], ah[mt], bl[nt][0], bl[nt][1]);
                    MMA_BF16(acc[mt][nt], al[mt], bh[nt][0], bh[nt][1]);
                }
            }
        }
        __syncthreads();
        if (c + 2 < NCH) prefetch(c + 2, stage);
        CP_COMMIT();
    }

    // Epilogue: fp32 stores
    const int gr = lane >> 2;          // 0..7
    const int gc = (lane & 3) * 2;     // 0,2,4,6
    const int row0 = m0 + warp_m * 64;
    const int col0 = n0 + warp_n * 32;
#pragma unroll
    for (int mt = 0; mt < 4; mt++) {
#pragma unroll
        for (int nt = 0; nt < 4; nt++) {
            float* p0 = Y + (size_t)(row0 + mt * 16 + gr) * KDIM + col0 + nt * 8 + gc;
            float* p1 = p0 + 8 * KDIM;
            asm volatile("st.global.v2.f32 [%0], {%1, %2};"
                :: "l"(p0), "f"(acc[mt][nt][0]), "f"(acc[mt][nt][1]) : "memory");
            asm volatile("st.global.v2.f32 [%0], {%1, %2};"
                :: "l"(p1), "f"(acc[mt][nt][2]), "f"(acc[mt][nt][3]) : "memory");
        }
    }
}

// ---------------------------------------------------------------------------
// Flash attention (fp32, causal). 64x64 tiles, dh=64, 256 threads. (unchanged)
// ---------------------------------------------------------------------------
#define TP 65
#define FA_TILE 64

__global__ __launch_bounds__(256)
void flash_attn_kernel(const float* __restrict__ Q, const float* __restrict__ Kg,
                       const float* __restrict__ Vg, float* __restrict__ O)
{
    extern __shared__ float sm[];
    float* Qs   = sm;
    float* Ks   = Qs + FA_TILE * TP;
    float* Vs   = Ks + FA_TILE * TP;
    float* Ps   = Vs + FA_TILE * TP;
    float* red  = Ps + FA_TILE * TP;
    float* rmax = red + FA_TILE * 16;
    float* rsum = rmax + FA_TILE;
    float* rfac = rsum + FA_TILE;

    const int tid = threadIdx.x;
    const int tx = tid & 15;
    const int ty = tid >> 4;
    const int mtile = blockIdx.x;
    const int bh = blockIdx.y;
    const int b = bh / H;
    const int h = bh % H;
    const int m0 = mtile * FA_TILE;

    const float* Qbase = Q  + (size_t)b * L * D + h * DH;
    const float* Kbase = Kg + (size_t)b * S * D + h * DH;
    const float* Vbase = Vg + (size_t)b * S * D + h * DH;

    const float scale = 0.125f;

    for (int idx = tid; idx < FA_TILE * DH; idx += 256) {
        int r = idx >> 6, c = idx & 63;
        Qs[r * TP + c] = Qbase[(size_t)(m0 + r) * D + c] * scale;
    }
    if (tid < 64) { rmax[tid] = -INFINITY; rsum[tid] = 0.f; }

    float Oacc[4][4];
#pragma unroll
    for (int i = 0; i < 4; i++)
#pragma unroll
        for (int j = 0; j < 4; j++) Oacc[i][j] = 0.f;

    __syncthreads();

    for (int jt = 0; jt <= mtile; jt++) {
        const int n0 = jt * FA_TILE;

        for (int idx = tid; idx < FA_TILE * DH; idx += 256) {
            int r = idx >> 6, c = idx & 63;
            Ks[r * TP + c] = Kbase[(size_t)(n0 + r) * D + c];
            Vs[r * TP + c] = Vbase[(size_t)(n0 + r) * D + c];
        }
        __syncthreads();

        float s[4][4];
#pragma unroll
        for (int i = 0; i < 4; i++)
#pragma unroll
            for (int j = 0; j < 4; j++) s[i][j] = 0.f;

#pragma unroll 16
        for (int d = 0; d < DH; d++) {
            float a[4], bb[4];
#pragma unroll
            for (int i = 0; i < 4; i++) a[i]  = Qs[(ty * 4 + i) * TP + d];
#pragma unroll
            for (int j = 0; j < 4; j++) bb[j] = Ks[(tx * 4 + j) * TP + d];
#pragma unroll
            for (int i = 0; i < 4; i++)
#pragma unroll
                for (int j = 0; j < 4; j++)
                    s[i][j] = fmaf(a[i], bb[j], s[i][j]);
        }

        if (jt == mtile) {
#pragma unroll
            for (int i = 0; i < 4; i++)
#pragma unroll
                for (int j = 0; j < 4; j++)
                    if (tx * 4 + j > ty * 4 + i) s[i][j] = -INFINITY;
        }

#pragma unroll
        for (int i = 0; i < 4; i++) {
            float mx = fmaxf(fmaxf(s[i][0], s[i][1]), fmaxf(s[i][2], s[i][3]));
            red[(ty * 4 + i) * 16 + tx] = mx;
        }
        __syncthreads();

        if (tid < 64) {
            float mx = red[tid * 16];
#pragma unroll
            for (int q = 1; q < 16; q++) mx = fmaxf(mx, red[tid * 16 + q]);
            float old = rmax[tid];
            float nm  = fmaxf(old, mx);
            rmax[tid] = nm;
            rfac[tid] = (old == -INFINITY) ? 0.f : __expf(old - nm);
        }
        __syncthreads();

#pragma unroll
        for (int i = 0; i < 4; i++) {
            float nm = rmax[ty * 4 + i];
            float f  = rfac[ty * 4 + i];
            float psum = 0.f;
#pragma unroll
            for (int j = 0; j < 4; j++) {
                float p = __expf(s[i][j] - nm);
                Ps[(ty * 4 + i) * TP + tx * 4 + j] = p;
                psum += p;
                Oacc[i][j] *= f;
            }
            red[(ty * 4 + i) * 16 + tx] = psum;
        }
        __syncthreads();

        if (tid < 64) {
            float sum = 0.f;
#pragma unroll
            for (int q = 0; q < 16; q++) sum += red[tid * 16 + q];
            rsum[tid] = rsum[tid] * rfac[tid] + sum;
        }

#pragma unroll 16
        for (int n = 0; n < FA_TILE; n++) {
            float p[4], vv[4];
#pragma unroll
            for (int i = 0; i < 4; i++) p[i]  = Ps[(ty * 4 + i) * TP + n];
#pragma unroll
            for (int j = 0; j < 4; j++) vv[j] = Vs[n * TP + tx * 4 + j];
#pragma unroll
            for (int i = 0; i < 4; i++)
#pragma unroll
                for (int j = 0; j < 4; j++)
                    Oacc[i][j] = fmaf(p[i], vv[j], Oacc[i][j]);
        }
        __syncthreads();
    }

    float* Obase = O + ((size_t)b * L + m0) * D + h * DH;
#pragma unroll
    for (int i = 0; i < 4; i++) {
        int m = ty * 4 + i;
        float inv = 1.f / rsum[m];
#pragma unroll
        for (int j = 0; j < 4; j++)
            Obase[(size_t)m * D + tx * 4 + j] = Oacc[i][j] * inv;
    }
}

// ---------------------------------------------------------------------------
// Launch
// ---------------------------------------------------------------------------
extern "C" void kernel_launch(void* const* d_in, const int* in_sizes, int n_in,
                              void* d_out, int out_size)
{
    const float* q_in = (const float*)d_in[0];
    const float* k_in = (const float*)d_in[1];
    const float* v_in = (const float*)d_in[2];
    const float* Wq   = (const float*)d_in[3];
    const float* Wk   = (const float*)d_in[4];
    const float* Wv   = (const float*)d_in[5];
    const float* Wo   = (const float*)d_in[6];
    float* out = (float*)d_out;

    float *gq, *gk, *gv, *gao;
    cudaGetSymbolAddress((void**)&gq,  g_q);
    cudaGetSymbolAddress((void**)&gk,  g_k);
    cudaGetSymbolAddress((void**)&gv,  g_v);
    cudaGetSymbolAddress((void**)&gao, g_ao);

    __nv_bfloat16 *ah, *al, *bh, *bl, *ch, *cl;
    __nv_bfloat16 *wqh, *wql, *wkh, *wkl, *wvh, *wvl, *woh, *wol;
    cudaGetSymbolAddress((void**)&ah, g_a_hi);
    cudaGetSymbolAddress((void**)&al, g_a_lo);
    cudaGetSymbolAddress((void**)&bh, g_b_hi);
    cudaGetSymbolAddress((void**)&bl, g_b_lo);
    cudaGetSymbolAddress((void**)&ch, g_c_hi);
    cudaGetSymbolAddress((void**)&cl, g_c_lo);
    cudaGetSymbolAddress((void**)&wqh, g_wq_hi);
    cudaGetSymbolAddress((void**)&wql, g_wq_lo);
    cudaGetSymbolAddress((void**)&wkh, g_wk_hi);
    cudaGetSymbolAddress((void**)&wkl, g_wk_lo);
    cudaGetSymbolAddress((void**)&wvh, g_wv_hi);
    cudaGetSymbolAddress((void**)&wvl, g_wv_lo);
    cudaGetSymbolAddress((void**)&woh, g_wo_hi);
    cudaGetSymbolAddress((void**)&wol, g_wo_lo);

    cudaFuncSetAttribute(gemm_mma_kernel,
                         cudaFuncAttributeMaxDynamicSharedMemorySize, GEMM_SMEM);
    const int fa_smem = (4 * FA_TILE * TP + FA_TILE * 16 + 3 * FA_TILE) * sizeof(float);
    cudaFuncSetAttribute(flash_attn_kernel,
                         cudaFuncAttributeMaxDynamicSharedMemorySize, fa_smem);

    const int Nrows = B * L;      // 8192
    const int nInp4 = Nrows * D / 4;
    const int nW4   = D * D / 4;
    const int cgrid_inp = (nInp4 + 255) / 256;
    const int cgrid_w   = (nW4 + 255) / 256;

    // Split weights + inputs to bf16 hi/lo
    split_bf16_kernel<<<cgrid_w, 256>>>(Wq, wqh, wql, nW4);
    split_bf16_kernel<<<cgrid_w, 256>>>(Wk, wkh, wkl, nW4);
    split_bf16_kernel<<<cgrid_w, 256>>>(Wv, wvh, wvl, nW4);
    split_bf16_kernel<<<cgrid_w, 256>>>(Wo, woh, wol, nW4);
    split_bf16_kernel<<<cgrid_inp, 256>>>(q_in, ah, al, nInp4);
    split_bf16_kernel<<<cgrid_inp, 256>>>(k_in, bh, bl, nInp4);
    split_bf16_kernel<<<cgrid_inp, 256>>>(v_in, ch, cl, nInp4);

    // Projections on tensor cores (HMMA)
    dim3 ggrid(D / 128, Nrows / 128);   // (8, 64)
    gemm_mma_kernel<<<ggrid, 256, GEMM_SMEM>>>(ah, al, wqh, wql, gq);
    gemm_mma_kernel<<<ggrid, 256, GEMM_SMEM>>>(bh, bl, wkh, wkl, gk);
    gemm_mma_kernel<<<ggrid, 256, GEMM_SMEM>>>(ch, cl, wvh, wvl, gv);

    // Flash attention (fp32)
    dim3 fa_grid(L / FA_TILE, B * H);
    flash_attn_kernel<<<fa_grid, 256, fa_smem>>>(gq, gk, gv, gao);

    // Output projection
    split_bf16_kernel<<<cgrid_inp, 256>>>(gao, ah, al, nInp4);
    gemm_mma_kernel<<<ggrid, 256, GEMM_SMEM>>>(ah, al, woh, wol, out);
}

// round 5
// speedup vs baseline: 2.6745x; 1.7847x over previous
#include <cuda_runtime.h>
#include <cuda_bf16.h>
#include <math.h>
#include <stdint.h>

// Problem constants
#define B 4
#define L 2048
#define S 2048
#define D 1024
#define H 16
#define DH 64

// ---------------------------------------------------------------------------
// Scratch (device globals — no allocation allowed)
// ---------------------------------------------------------------------------
// input splits
__device__ __nv_bfloat16 g_ain_hi[B * L * D];
__device__ __nv_bfloat16 g_ain_lo[B * L * D];
__device__ __nv_bfloat16 g_bin_hi[B * L * D];
__device__ __nv_bfloat16 g_bin_lo[B * L * D];
__device__ __nv_bfloat16 g_cin_hi[B * L * D];
__device__ __nv_bfloat16 g_cin_lo[B * L * D];
// weight splits
__device__ __nv_bfloat16 g_wq_hi[D * D];
__device__ __nv_bfloat16 g_wq_lo[D * D];
__device__ __nv_bfloat16 g_wk_hi[D * D];
__device__ __nv_bfloat16 g_wk_lo[D * D];
__device__ __nv_bfloat16 g_wv_hi[D * D];
__device__ __nv_bfloat16 g_wv_lo[D * D];
__device__ __nv_bfloat16 g_wo_hi[D * D];
__device__ __nv_bfloat16 g_wo_lo[D * D];
// projected Q/K/V and attention output, bf16 hi/lo
__device__ __nv_bfloat16 g_q_hi[B * L * D];
__device__ __nv_bfloat16 g_q_lo[B * L * D];
__device__ __nv_bfloat16 g_k_hi[B * S * D];
__device__ __nv_bfloat16 g_k_lo[B * S * D];
__device__ __nv_bfloat16 g_v_hi[B * S * D];
__device__ __nv_bfloat16 g_v_lo[B * S * D];
__device__ __nv_bfloat16 g_o_hi[B * L * D];
__device__ __nv_bfloat16 g_o_lo[B * L * D];

// ---------------------------------------------------------------------------
// Helpers (baseline compute_103-safe PTX only)
// ---------------------------------------------------------------------------
__device__ __forceinline__ uint32_t smem_u32(const void* p) {
    uint32_t a;
    asm("{ .reg .u64 t; cvta.to.shared.u64 t, %1; cvt.u32.u64 %0, t; }"
        : "=r"(a) : "l"(p));
    return a;
}

#define CP16(dst, src) \
    asm volatile("cp.async.cg.shared.global [%0], [%1], 16;" \
        :: "r"(dst), "l"(src) : "memory")

#define CP_COMMIT() asm volatile("cp.async.commit_group;" ::: "memory")
#define CP_WAIT1()  asm volatile("cp.async.wait_group 1;" ::: "memory")

#define LDSM_X4(r0, r1, r2, r3, addr) \
    asm volatile("ldmatrix.sync.aligned.m8n8.x4.shared.b16 {%0,%1,%2,%3}, [%4];" \
        : "=r"(r0), "=r"(r1), "=r"(r2), "=r"(r3) : "r"(addr))

#define LDSM_X4_T(r0, r1, r2, r3, addr) \
    asm volatile("ldmatrix.sync.aligned.m8n8.x4.trans.shared.b16 {%0,%1,%2,%3}, [%4];" \
        : "=r"(r0), "=r"(r1), "=r"(r2), "=r"(r3) : "r"(addr))

#define MMA_BF16(c, a, b0, b1) \
    asm volatile("mma.sync.aligned.m16n8k16.row.col.f32.bf16.bf16.f32 " \
        "{%0,%1,%2,%3}, {%4,%5,%6,%7}, {%8,%9}, {%0,%1,%2,%3};" \
        : "+f"((c)[0]), "+f"((c)[1]), "+f"((c)[2]), "+f"((c)[3]) \
        : "r"((a)[0]), "r"((a)[1]), "r"((a)[2]), "r"((a)[3]), \
          "r"(b0), "r"(b1))

__device__ __forceinline__ float ex2f(float x) {
    float r;
    asm("ex2.approx.f32 %0, %1;" : "=f"(r) : "f"(x));
    return r;
}

// pack two fp32 -> bf16x2 (lo in lower half)
__device__ __forceinline__ uint32_t pack_bf16x2(float lo, float hi) {
    uint32_t r;
    asm("cvt.rn.bf16x2.f32 %0, %1, %2;" : "=r"(r) : "f"(hi), "f"(lo));
    return r;
}

// split fp32 pair into bf16 hi-pack and lo-pack
__device__ __forceinline__ void split_pack(float v0, float v1,
                                           uint32_t& hp, uint32_t& lp) {
    __nv_bfloat16 h0 = __float2bfloat16(v0);
    __nv_bfloat16 h1 = __float2bfloat16(v1);
    __nv_bfloat162 hh(h0, h1);
    hp = *reinterpret_cast<uint32_t*>(&hh);
    lp = pack_bf16x2(v0 - __bfloat162float(h0), v1 - __bfloat162float(h1));
}

// ---------------------------------------------------------------------------
// fp32 -> (bf16 hi, bf16 lo) split kernel.
// ---------------------------------------------------------------------------
__global__ __launch_bounds__(256)
void split_bf16_kernel(const float* __restrict__ x,
                       __nv_bfloat16* __restrict__ hi,
                       __nv_bfloat16* __restrict__ lo, int n4)
{
    int i = blockIdx.x * blockDim.x + threadIdx.x;
    if (i >= n4) return;
    float4 v = reinterpret_cast<const float4*>(x)[i];
    uint2 hv, lv;
    split_pack(v.x, v.y, hv.x, lv.x);
    split_pack(v.z, v.w, hv.y, lv.y);
    reinterpret_cast<uint2*>(hi)[i] = hv;
    reinterpret_cast<uint2*>(lo)[i] = lv;
}

// ---------------------------------------------------------------------------
// HMMA split-bf16 GEMM:  Y[m, n] = sum_k A[m,k] * W[n,k]
// CTA tile 128x128, warp tile 64x32 (8 warps as 2x4), k-chunk 32, 2 stages.
// BF16OUT: epilogue emits (bf16 hi, bf16 lo) of acc*scale; else fp32.
// ---------------------------------------------------------------------------
#define KDIM 1024
#define NCH 32
#define PITCH 80
#define TSZ (128 * PITCH)
#define STAGE_B (4 * TSZ)
#define GEMM_SMEM (2 * STAGE_B)

template<bool BF16OUT>
__global__ __launch_bounds__(256, 1)
void gemm_mma_kernel(const __nv_bfloat16* __restrict__ Ahi,
                     const __nv_bfloat16* __restrict__ Alo,
                     const __nv_bfloat16* __restrict__ Whi,
                     const __nv_bfloat16* __restrict__ Wlo,
                     float* __restrict__ Yf,
                     __nv_bfloat16* __restrict__ Yhi,
                     __nv_bfloat16* __restrict__ Ylo,
                     float scale)
{
    extern __shared__ char smem[];
    const uint32_t sb = smem_u32(smem);
    const int tid = threadIdx.x;
    const int lane = tid & 31;
    const int wid = tid >> 5;
    const int warp_m = wid >> 2;
    const int warp_n = wid & 3;
    const int m0 = blockIdx.y * 128;
    const int n0 = blockIdx.x * 128;

    float acc[4][4][4];
#pragma unroll
    for (int a = 0; a < 4; a++)
#pragma unroll
        for (int b = 0; b < 4; b++)
#pragma unroll
            for (int c = 0; c < 4; c++) acc[a][b][c] = 0.f;

    auto prefetch = [&](int c, int stage) {
        const uint32_t sbase = sb + stage * STAGE_B;
        const int k0 = c * 32;
#pragma unroll
        for (int j = 0; j < 2; j++) {
            const int idx = j * 256 + tid;
            const int r  = (idx & 7) + (idx >> 5) * 8;
            const int ch = (idx >> 3) & 3;
            const uint32_t so = (uint32_t)(r * PITCH + ch * 16);
            const char* ga_hi = (const char*)(Ahi + (size_t)(m0 + r) * KDIM + k0) + ch * 16;
            const char* ga_lo = (const char*)(Alo + (size_t)(m0 + r) * KDIM + k0) + ch * 16;
            const char* gb_hi = (const char*)(Whi + (size_t)(n0 + r) * KDIM + k0) + ch * 16;
            const char* gb_lo = (const char*)(Wlo + (size_t)(n0 + r) * KDIM + k0) + ch * 16;
            CP16(sbase + so,           ga_hi);
            CP16(sbase + TSZ + so,     ga_lo);
            CP16(sbase + 2 * TSZ + so, gb_hi);
            CP16(sbase + 3 * TSZ + so, gb_lo);
        }
    };

    prefetch(0, 0); CP_COMMIT();
    prefetch(1, 1); CP_COMMIT();

    for (int c = 0; c < NCH; c++) {
        const int stage = c & 1;
        CP_WAIT1();
        __syncthreads();
        const uint32_t sbase = sb + stage * STAGE_B;

#pragma unroll
        for (int s = 0; s < 2; s++) {
            uint32_t ah[4][4], al[4][4], bh[4][2], bl[4][2];
            const int lr = lane & 15;
            const int lh = lane >> 4;
#pragma unroll
            for (int mt = 0; mt < 4; mt++) {
                const uint32_t ad = sbase +
                    (uint32_t)((warp_m * 64 + mt * 16 + lr) * PITCH + s * 32 + lh * 16);
                LDSM_X4(ah[mt][0], ah[mt][1], ah[mt][2], ah[mt][3], ad);
                LDSM_X4(al[mt][0], al[mt][1], al[mt][2], al[mt][3], ad + TSZ);
            }
            const int br = (lane & 7) + ((lane >> 4) & 1) * 8;
            const int bk = ((lane >> 3) & 1) * 16;
#pragma unroll
            for (int np = 0; np < 2; np++) {
                const uint32_t bd = sbase + 2 * TSZ +
                    (uint32_t)((warp_n * 32 + np * 16 + br) * PITCH + s * 32 + bk);
                uint32_t t0, t1, t2, t3;
                LDSM_X4(t0, t1, t2, t3, bd);
                bh[np * 2][0] = t0; bh[np * 2][1] = t1;
                bh[np * 2 + 1][0] = t2; bh[np * 2 + 1][1] = t3;
                LDSM_X4(t0, t1, t2, t3, bd + TSZ);
                bl[np * 2][0] = t0; bl[np * 2][1] = t1;
                bl[np * 2 + 1][0] = t2; bl[np * 2 + 1][1] = t3;
            }
#pragma unroll
            for (int mt = 0; mt < 4; mt++) {
#pragma unroll
                for (int nt = 0; nt < 4; nt++) {
                    MMA_BF16(acc[mt][nt], ah[mt], bh[nt][0], bh[nt][1]);
                    MMA_BF16(acc[mt][nt], ah[mt], bl[nt][0], bl[nt][1]);
                    MMA_BF16(acc[mt][nt], al[mt], bh[nt][0], bh[nt][1]);
                }
            }
        }
        __syncthreads();
        if (c + 2 < NCH) prefetch(c + 2, stage);
        CP_COMMIT();
    }

    const int gr = lane >> 2;
    const int gc = (lane & 3) * 2;
    const int row0 = m0 + warp_m * 64;
    const int col0 = n0 + warp_n * 32;
#pragma unroll
    for (int mt = 0; mt < 4; mt++) {
#pragma unroll
        for (int nt = 0; nt < 4; nt++) {
            const int r0 = row0 + mt * 16 + gr;
            const int cc = col0 + nt * 8 + gc;
            if (BF16OUT) {
                uint32_t hp, lp;
                split_pack(acc[mt][nt][0] * scale, acc[mt][nt][1] * scale, hp, lp);
                *reinterpret_cast<uint32_t*>(Yhi + (size_t)r0 * KDIM + cc) = hp;
                *reinterpret_cast<uint32_t*>(Ylo + (size_t)r0 * KDIM + cc) = lp;
                split_pack(acc[mt][nt][2] * scale, acc[mt][nt][3] * scale, hp, lp);
                *reinterpret_cast<uint32_t*>(Yhi + (size_t)(r0 + 8) * KDIM + cc) = hp;
                *reinterpret_cast<uint32_t*>(Ylo + (size_t)(r0 + 8) * KDIM + cc) = lp;
            } else {
                float* p0 = Yf + (size_t)r0 * KDIM + cc;
                float* p1 = p0 + 8 * KDIM;
                asm volatile("st.global.v2.f32 [%0], {%1, %2};"
                    :: "l"(p0), "f"(acc[mt][nt][0]), "f"(acc[mt][nt][1]) : "memory");
                asm volatile("st.global.v2.f32 [%0], {%1, %2};"
                    :: "l"(p1), "f"(acc[mt][nt][2]), "f"(acc[mt][nt][3]) : "memory");
            }
        }
    }
}

// ---------------------------------------------------------------------------
// HMMA flash attention (causal), split-bf16 inputs, log2-domain softmax.
// CTA: 128 q-rows (8 warps x 16), kv-tiles of 64, dh=64.
// Q pre-scaled by 0.125*log2(e) at the projection epilogue.
// ---------------------------------------------------------------------------
#define APITCH 144
#define AQT (128 * APITCH)       // 18432
#define AKT (64 * APITCH)        // 9216
#define ASTG (4 * AKT)           // 36864
#define ATTN_SMEM (2 * AQT + 2 * ASTG)   // 110592

__global__ __launch_bounds__(256, 1)
void attn_mma_kernel(const __nv_bfloat16* __restrict__ Qhi,
                     const __nv_bfloat16* __restrict__ Qlo,
                     const __nv_bfloat16* __restrict__ Khi,
                     const __nv_bfloat16* __restrict__ Klo,
                     const __nv_bfloat16* __restrict__ Vhi,
                     const __nv_bfloat16* __restrict__ Vlo,
                     __nv_bfloat16* __restrict__ Ohi,
                     __nv_bfloat16* __restrict__ Olo)
{
    extern __shared__ char smem[];
    const uint32_t sb = smem_u32(smem);
    const int tid = threadIdx.x;
    const int lane = tid & 31;
    const int wid = tid >> 5;
    const int mq = (L / 128 - 1) - blockIdx.x;     // heavy tiles first
    const int bh = blockIdx.y;
    const int b = bh >> 4;
    const int h = bh & 15;
    const int m0 = mq * 128;
    const int ntiles = mq * 2 + 2;

    const size_t qg = ((size_t)b * L + m0) * D + h * DH;
    const size_t kg = (size_t)b * S * D + h * DH;

    // --- Q prefetch (group 0) ---
#pragma unroll
    for (int i = 0; i < 8; i++) {
        const int idx = i * 256 + tid;
        const int tsr = idx >> 10;             // 0 hi, 1 lo
        const int rem = idx & 1023;
        const int row = rem >> 3;
        const int ch = rem & 7;
        const __nv_bfloat16* src = (tsr ? Qlo : Qhi) + qg + (size_t)row * D + ch * 8;
        CP16(sb + tsr * AQT + row * APITCH + ch * 16, src);
    }

    auto prefetch_kv = [&](int j, int stage) {
        const int n0 = j * 64;
#pragma unroll
        for (int i = 0; i < 8; i++) {
            const int idx = i * 256 + tid;
            const int tsr = idx >> 9;           // 0 khi 1 klo 2 vhi 3 vlo
            const int rem = idx & 511;
            const int row = rem >> 3;
            const int ch = rem & 7;
            const __nv_bfloat16* base =
                (tsr == 0) ? Khi : (tsr == 1) ? Klo : (tsr == 2) ? Vhi : Vlo;
            const __nv_bfloat16* src = base + kg + (size_t)(n0 + row) * D + ch * 8;
            CP16(sb + 2 * AQT + stage * ASTG + tsr * AKT + row * APITCH + ch * 16, src);
        }
    };

    prefetch_kv(0, 0); CP_COMMIT();
    prefetch_kv(1, 1); CP_COMMIT();

    float oacc[8][4];
#pragma unroll
    for (int j = 0; j < 8; j++)
#pragma unroll
        for (int e = 0; e < 4; e++) oacc[j][e] = 0.f;

    float m1 = -INFINITY, m2 = -INFINITY, l1 = 0.f, l2 = 0.f;
    uint32_t qh[4][4], ql[4][4];
    bool qloaded = false;

    const int lr = lane & 15;
    const int lh = lane >> 4;
    const int br = (lane & 7) + ((lane >> 4) & 1) * 8;
    const int bk = ((lane >> 3) & 1) * 16;
    const int vs_off = ((lane >> 3) & 1) * 8 + (lane & 7);
    const int vdb = (lane >> 4) * 16;
    const int qbw = m0 + wid * 16;            // warp's q-row base

    for (int jt = 0; jt < ntiles; jt++) {
        const int stage = jt & 1;
        CP_WAIT1();
        __syncthreads();
        const uint32_t kbase = sb + 2 * AQT + stage * ASTG;
        const uint32_t vbase = kbase + 2 * AKT;

        if (!qloaded) {
            qloaded = true;
#pragma unroll
            for (int ks = 0; ks < 4; ks++) {
                const uint32_t ad = sb +
                    (uint32_t)((wid * 16 + lr) * APITCH + ks * 32 + lh * 16);
                LDSM_X4(qh[ks][0], qh[ks][1], qh[ks][2], qh[ks][3], ad);
                LDSM_X4(ql[ks][0], ql[ks][1], ql[ks][2], ql[ks][3], ad + AQT);
            }
        }

        // ---- S = Q K^T ----
        float sacc[8][4];
#pragma unroll
        for (int j = 0; j < 8; j++)
#pragma unroll
            for (int e = 0; e < 4; e++) sacc[j][e] = 0.f;

#pragma unroll
        for (int ks = 0; ks < 4; ks++) {
#pragma unroll
            for (int np = 0; np < 4; np++) {
                const uint32_t bd = kbase +
                    (uint32_t)((np * 16 + br) * APITCH + ks * 32 + bk);
                uint32_t t0, t1, t2, t3, u0, u1, u2, u3;
                LDSM_X4(t0, t1, t2, t3, bd);
                LDSM_X4(u0, u1, u2, u3, bd + AKT);
                MMA_BF16(sacc[np * 2], qh[ks], t0, t1);
                MMA_BF16(sacc[np * 2], qh[ks], u0, u1);
                MMA_BF16(sacc[np * 2], ql[ks], t0, t1);
                MMA_BF16(sacc[np * 2 + 1], qh[ks], t2, t3);
                MMA_BF16(sacc[np * 2 + 1], qh[ks], u2, u3);
                MMA_BF16(sacc[np * 2 + 1], ql[ks], t2, t3);
            }
        }

        // ---- causal mask (only near diagonal) ----
        const int n0 = jt * 64;
        if (n0 + 63 > qbw) {
            const int r1 = qbw + (lane >> 2);
            const int r2 = r1 + 8;
#pragma unroll
            for (int j = 0; j < 8; j++) {
                const int c0 = n0 + j * 8 + (lane & 3) * 2;
                if (c0 > r1) sacc[j][0] = -INFINITY;
                if (c0 + 1 > r1) sacc[j][1] = -INFINITY;
                if (c0 > r2) sacc[j][2] = -INFINITY;
                if (c0 + 1 > r2) sacc[j][3] = -INFINITY;
            }
        }

        // ---- online softmax (log2 domain) ----
        float mt1 = -INFINITY, mt2 = -INFINITY;
#pragma unroll
        for (int j = 0; j < 8; j++) {
            mt1 = fmaxf(mt1, fmaxf(sacc[j][0], sacc[j][1]));
            mt2 = fmaxf(mt2, fmaxf(sacc[j][2], sacc[j][3]));
        }
        mt1 = fmaxf(mt1, __shfl_xor_sync(0xFFFFFFFFu, mt1, 1));
        mt1 = fmaxf(mt1, __shfl_xor_sync(0xFFFFFFFFu, mt1, 2));
        mt2 = fmaxf(mt2, __shfl_xor_sync(0xFFFFFFFFu, mt2, 1));
        mt2 = fmaxf(mt2, __shfl_xor_sync(0xFFFFFFFFu, mt2, 2));

        const float nm1 = fmaxf(m1, mt1);
        const float nm2 = fmaxf(m2, mt2);
        const float f1 = ex2f(m1 - nm1);    // ex2(-inf)=0 on first tile
        const float f2 = ex2f(m2 - nm2);
        m1 = nm1; m2 = nm2;

        float rs1 = 0.f, rs2 = 0.f;
#pragma unroll
        for (int j = 0; j < 8; j++) {
            sacc[j][0] = ex2f(sacc[j][0] - nm1);
            sacc[j][1] = ex2f(sacc[j][1] - nm1);
            sacc[j][2] = ex2f(sacc[j][2] - nm2);
            sacc[j][3] = ex2f(sacc[j][3] - nm2);
            rs1 += sacc[j][0] + sacc[j][1];
            rs2 += sacc[j][2] + sacc[j][3];
        }
        rs1 += __shfl_xor_sync(0xFFFFFFFFu, rs1, 1);
        rs1 += __shfl_xor_sync(0xFFFFFFFFu, rs1, 2);
        rs2 += __shfl_xor_sync(0xFFFFFFFFu, rs2, 1);
        rs2 += __shfl_xor_sync(0xFFFFFFFFu, rs2, 2);
        l1 = l1 * f1 + rs1;
        l2 = l2 * f2 + rs2;

#pragma unroll
        for (int j = 0; j < 8; j++) {
            oacc[j][0] *= f1; oacc[j][1] *= f1;
            oacc[j][2] *= f2; oacc[j][3] *= f2;
        }

        // ---- O += P V ----
#pragma unroll
        for (int t = 0; t < 4; t++) {
            uint32_t ph[4], pl[4];
            split_pack(sacc[2 * t][0], sacc[2 * t][1], ph[0], pl[0]);
            split_pack(sacc[2 * t][2], sacc[2 * t][3], ph[1], pl[1]);
            split_pack(sacc[2 * t + 1][0], sacc[2 * t + 1][1], ph[2], pl[2]);
            split_pack(sacc[2 * t + 1][2], sacc[2 * t + 1][3], ph[3], pl[3]);
#pragma unroll
            for (int dp = 0; dp < 4; dp++) {
                const uint32_t vd = vbase +
                    (uint32_t)((t * 16 + vs_off) * APITCH + vdb + dp * 32);
                uint32_t t0, t1, t2, t3, u0, u1, u2, u3;
                LDSM_X4_T(t0, t1, t2, t3, vd);
                LDSM_X4_T(u0, u1, u2, u3, vd + AKT);
                MMA_BF16(oacc[dp * 2], ph, t0, t1);
                MMA_BF16(oacc[dp * 2], ph, u0, u1);
                MMA_BF16(oacc[dp * 2], pl, t0, t1);
                MMA_BF16(oacc[dp * 2 + 1], ph, t2, t3);
                MMA_BF16(oacc[dp * 2 + 1], ph, u2, u3);
                MMA_BF16(oacc[dp * 2 + 1], pl, t2, t3);
            }
        }

        __syncthreads();
        if (jt + 2 < ntiles) prefetch_kv(jt + 2, stage);
        CP_COMMIT();
    }

    // ---- epilogue ----
    const float inv1 = 1.f / l1;
    const float inv2 = 1.f / l2;
    const int r1 = m0 + wid * 16 + (lane >> 2);
    const int r2 = r1 + 8;
    const int cbase = h * DH + (lane & 3) * 2;
#pragma unroll
    for (int j = 0; j < 8; j++) {
        const int cc = cbase + j * 8;
        uint32_t hp, lp;
        split_pack(oacc[j][0] * inv1, oacc[j][1] * inv1, hp, lp);
        *reinterpret_cast<uint32_t*>(Ohi + ((size_t)b * L + r1) * D + cc) = hp;
        *reinterpret_cast<uint32_t*>(Olo + ((size_t)b * L + r1) * D + cc) = lp;
        split_pack(oacc[j][2] * inv2, oacc[j][3] * inv2, hp, lp);
        *reinterpret_cast<uint32_t*>(Ohi + ((size_t)b * L + r2) * D + cc) = hp;
        *reinterpret_cast<uint32_t*>(Olo + ((size_t)b * L + r2) * D + cc) = lp;
    }
}

// ---------------------------------------------------------------------------
// Launch
// ---------------------------------------------------------------------------
extern "C" void kernel_launch(void* const* d_in, const int* in_sizes, int n_in,
                              void* d_out, int out_size)
{
    const float* q_in = (const float*)d_in[0];
    const float* k_in = (const float*)d_in[1];
    const float* v_in = (const float*)d_in[2];
    const float* Wq   = (const float*)d_in[3];
    const float* Wk   = (const float*)d_in[4];
    const float* Wv   = (const float*)d_in[5];
    const float* Wo   = (const float*)d_in[6];
    float* out = (float*)d_out;

    __nv_bfloat16 *ainh, *ainl, *binh, *binl, *cinh, *cinl;
    __nv_bfloat16 *wqh, *wql, *wkh, *wkl, *wvh, *wvl, *woh, *wol;
    __nv_bfloat16 *qh, *qlp, *kh, *kl, *vh, *vl, *oh, *ol;
    cudaGetSymbolAddress((void**)&ainh, g_ain_hi);
    cudaGetSymbolAddress((void**)&ainl, g_ain_lo);
    cudaGetSymbolAddress((void**)&binh, g_bin_hi);
    cudaGetSymbolAddress((void**)&binl, g_bin_lo);
    cudaGetSymbolAddress((void**)&cinh, g_cin_hi);
    cudaGetSymbolAddress((void**)&cinl, g_cin_lo);
    cudaGetSymbolAddress((void**)&wqh, g_wq_hi);
    cudaGetSymbolAddress((void**)&wql, g_wq_lo);
    cudaGetSymbolAddress((void**)&wkh, g_wk_hi);
    cudaGetSymbolAddress((void**)&wkl, g_wk_lo);
    cudaGetSymbolAddress((void**)&wvh, g_wv_hi);
    cudaGetSymbolAddress((void**)&wvl, g_wv_lo);
    cudaGetSymbolAddress((void**)&woh, g_wo_hi);
    cudaGetSymbolAddress((void**)&wol, g_wo_lo);
    cudaGetSymbolAddress((void**)&qh, g_q_hi);
    cudaGetSymbolAddress((void**)&qlp, g_q_lo);
    cudaGetSymbolAddress((void**)&kh, g_k_hi);
    cudaGetSymbolAddress((void**)&kl, g_k_lo);
    cudaGetSymbolAddress((void**)&vh, g_v_hi);
    cudaGetSymbolAddress((void**)&vl, g_v_lo);
    cudaGetSymbolAddress((void**)&oh, g_o_hi);
    cudaGetSymbolAddress((void**)&ol, g_o_lo);

    cudaFuncSetAttribute(gemm_mma_kernel<true>,
                         cudaFuncAttributeMaxDynamicSharedMemorySize, GEMM_SMEM);
    cudaFuncSetAttribute(gemm_mma_kernel<false>,
                         cudaFuncAttributeMaxDynamicSharedMemorySize, GEMM_SMEM);
    cudaFuncSetAttribute(attn_mma_kernel,
                         cudaFuncAttributeMaxDynamicSharedMemorySize, ATTN_SMEM);

    const int Nrows = B * L;
    const int nInp4 = Nrows * D / 4;
    const int nW4   = D * D / 4;
    const int cgrid_inp = (nInp4 + 255) / 256;
    const int cgrid_w   = (nW4 + 255) / 256;

    split_bf16_kernel<<<cgrid_w, 256>>>(Wq, wqh, wql, nW4);
    split_bf16_kernel<<<cgrid_w, 256>>>(Wk, wkh, wkl, nW4);
    split_bf16_kernel<<<cgrid_w, 256>>>(Wv, wvh, wvl, nW4);
    split_bf16_kernel<<<cgrid_w, 256>>>(Wo, woh, wol, nW4);
    split_bf16_kernel<<<cgrid_inp, 256>>>(q_in, ainh, ainl, nInp4);
    split_bf16_kernel<<<cgrid_inp, 256>>>(k_in, binh, binl, nInp4);
    split_bf16_kernel<<<cgrid_inp, 256>>>(v_in, cinh, cinl, nInp4);

    dim3 ggrid(D / 128, Nrows / 128);
    // Q projection: fold softmax scale 1/8 and log2(e) into Q
    const float qscale = 0.125f * 1.4426950408889634f;
    gemm_mma_kernel<true><<<ggrid, 256, GEMM_SMEM>>>(ainh, ainl, wqh, wql,
                                                     nullptr, qh, qlp, qscale);
    gemm_mma_kernel<true><<<ggrid, 256, GEMM_SMEM>>>(binh, binl, wkh, wkl,
                                                     nullptr, kh, kl, 1.f);
    gemm_mma_kernel<true><<<ggrid, 256, GEMM_SMEM>>>(cinh, cinl, wvh, wvl,
                                                     nullptr, vh, vl, 1.f);

    dim3 agrid(L / 128, B * H);
    attn_mma_kernel<<<agrid, 256, ATTN_SMEM>>>(qh, qlp, kh, kl, vh, vl, oh, ol);

    gemm_mma_kernel<false><<<ggrid, 256, GEMM_SMEM>>>(oh, ol, woh, wol,
                                                      out, nullptr, nullptr, 1.f);
}

// round 9
// speedup vs baseline: 3.0516x; 1.1410x over previous
#include <cuda_runtime.h>
#include <cuda_bf16.h>
#include <math.h>
#include <stdint.h>

// Problem constants
#define B 4
#define L 2048
#define S 2048
#define D 1024
#define H 16
#define DH 64

// ---------------------------------------------------------------------------
// Scratch (device globals — no allocation allowed)
// ---------------------------------------------------------------------------
__device__ __nv_bfloat16 g_ain_hi[B * L * D];
__device__ __nv_bfloat16 g_ain_lo[B * L * D];
__device__ __nv_bfloat16 g_bin_hi[B * L * D];
__device__ __nv_bfloat16 g_bin_lo[B * L * D];
__device__ __nv_bfloat16 g_cin_hi[B * L * D];
__device__ __nv_bfloat16 g_cin_lo[B * L * D];
__device__ __nv_bfloat16 g_wq_hi[D * D];
__device__ __nv_bfloat16 g_wq_lo[D * D];
__device__ __nv_bfloat16 g_wk_hi[D * D];
__device__ __nv_bfloat16 g_wk_lo[D * D];
__device__ __nv_bfloat16 g_wv_hi[D * D];
__device__ __nv_bfloat16 g_wv_lo[D * D];
__device__ __nv_bfloat16 g_wo_hi[D * D];
__device__ __nv_bfloat16 g_wo_lo[D * D];
__device__ __nv_bfloat16 g_q_hi[B * L * D];
__device__ __nv_bfloat16 g_q_lo[B * L * D];
__device__ __nv_bfloat16 g_k_hi[B * S * D];
__device__ __nv_bfloat16 g_k_lo[B * S * D];
__device__ __nv_bfloat16 g_v_hi[B * S * D];
__device__ __nv_bfloat16 g_v_lo[B * S * D];
__device__ __nv_bfloat16 g_o_hi[B * L * D];
__device__ __nv_bfloat16 g_o_lo[B * L * D];

// ---------------------------------------------------------------------------
// Helpers (baseline compute_103-safe PTX only)
// ---------------------------------------------------------------------------
__device__ __forceinline__ uint32_t smem_u32(const void* p) {
    uint32_t a;
    asm("{ .reg .u64 t; cvta.to.shared.u64 t, %1; cvt.u32.u64 %0, t; }"
        : "=r"(a) : "l"(p));
    return a;
}

#define CP16(dst, src) \
    asm volatile("cp.async.cg.shared.global [%0], [%1], 16;" \
        :: "r"(dst), "l"(src) : "memory")

#define CP_COMMIT() asm volatile("cp.async.commit_group;" ::: "memory")
#define CP_WAIT1()  asm volatile("cp.async.wait_group 1;" ::: "memory")

#define LDSM_X4(r0, r1, r2, r3, addr) \
    asm volatile("ldmatrix.sync.aligned.m8n8.x4.shared.b16 {%0,%1,%2,%3}, [%4];" \
        : "=r"(r0), "=r"(r1), "=r"(r2), "=r"(r3) : "r"(addr))

#define LDSM_X4_T(r0, r1, r2, r3, addr) \
    asm volatile("ldmatrix.sync.aligned.m8n8.x4.trans.shared.b16 {%0,%1,%2,%3}, [%4];" \
        : "=r"(r0), "=r"(r1), "=r"(r2), "=r"(r3) : "r"(addr))

#define MMA_BF16(c, a, b0, b1) \
    asm volatile("mma.sync.aligned.m16n8k16.row.col.f32.bf16.bf16.f32 " \
        "{%0,%1,%2,%3}, {%4,%5,%6,%7}, {%8,%9}, {%0,%1,%2,%3};" \
        : "+f"((c)[0]), "+f"((c)[1]), "+f"((c)[2]), "+f"((c)[3]) \
        : "r"((a)[0]), "r"((a)[1]), "r"((a)[2]), "r"((a)[3]), \
          "r"(b0), "r"(b1))

__device__ __forceinline__ float ex2f(float x) {
    float r;
    asm("ex2.approx.f32 %0, %1;" : "=f"(r) : "f"(x));
    return r;
}

__device__ __forceinline__ uint32_t pack_bf16x2(float lo, float hi) {
    uint32_t r;
    asm("cvt.rn.bf16x2.f32 %0, %1, %2;" : "=r"(r) : "f"(hi), "f"(lo));
    return r;
}

__device__ __forceinline__ void split_pack(float v0, float v1,
                                           uint32_t& hp, uint32_t& lp) {
    __nv_bfloat16 h0 = __float2bfloat16(v0);
    __nv_bfloat16 h1 = __float2bfloat16(v1);
    __nv_bfloat162 hh(h0, h1);
    hp = *reinterpret_cast<uint32_t*>(&hh);
    lp = pack_bf16x2(v0 - __bfloat162float(h0), v1 - __bfloat162float(h1));
}

// ---------------------------------------------------------------------------
// Split kernels (merged: weights x4, inputs x3; outputs are device symbols)
// ---------------------------------------------------------------------------
__device__ __forceinline__ void split_body(const float* __restrict__ x,
                                           __nv_bfloat16* __restrict__ hi,
                                           __nv_bfloat16* __restrict__ lo, int n4)
{
    int i = blockIdx.x * blockDim.x + threadIdx.x;
    if (i >= n4) return;
    float4 v = reinterpret_cast<const float4*>(x)[i];
    uint2 hv, lv;
    split_pack(v.x, v.y, hv.x, lv.x);
    split_pack(v.z, v.w, hv.y, lv.y);
    reinterpret_cast<uint2*>(hi)[i] = hv;
    reinterpret_cast<uint2*>(lo)[i] = lv;
}

__global__ __launch_bounds__(256)
void split_w4_kernel(const float* __restrict__ Wq, const float* __restrict__ Wk,
                     const float* __restrict__ Wv, const float* __restrict__ Wo)
{
    const int seg = blockIdx.y;
    const float* src = (seg == 0) ? Wq : (seg == 1) ? Wk : (seg == 2) ? Wv : Wo;
    __nv_bfloat16* hi = (seg == 0) ? g_wq_hi : (seg == 1) ? g_wk_hi
                       : (seg == 2) ? g_wv_hi : g_wo_hi;
    __nv_bfloat16* lo = (seg == 0) ? g_wq_lo : (seg == 1) ? g_wk_lo
                       : (seg == 2) ? g_wv_lo : g_wo_lo;
    split_body(src, hi, lo, D * D / 4);
}

__global__ __launch_bounds__(256)
void split_in3_kernel(const float* __restrict__ q, const float* __restrict__ k,
                      const float* __restrict__ v)
{
    const int seg = blockIdx.y;
    const float* src = (seg == 0) ? q : (seg == 1) ? k : v;
    __nv_bfloat16* hi = (seg == 0) ? g_ain_hi : (seg == 1) ? g_bin_hi : g_cin_hi;
    __nv_bfloat16* lo = (seg == 0) ? g_ain_lo : (seg == 1) ? g_bin_lo : g_cin_lo;
    split_body(src, hi, lo, B * L * D / 4);
}

// ---------------------------------------------------------------------------
// HMMA split-bf16 GEMM:  Y[m, n] = sum_k A[m,k] * W[n,k]
// CTA tile 128x128, warp tile 64x32 (8 warps as 2x4), k-chunk 32.
// 3-stage cp.async ring, prefetch distance 2, ONE barrier per iteration.
// ---------------------------------------------------------------------------
#define KDIM 1024
#define NCH 32
#define PITCH 80
#define TSZ (128 * PITCH)
#define STAGE_B (4 * TSZ)
#define GEMM_SMEM (3 * STAGE_B)   // 122880 B

template<bool BF16OUT>
__global__ __launch_bounds__(256, 1)
void gemm_mma_kernel(const __nv_bfloat16* __restrict__ Ahi,
                     const __nv_bfloat16* __restrict__ Alo,
                     const __nv_bfloat16* __restrict__ Whi,
                     const __nv_bfloat16* __restrict__ Wlo,
                     float* __restrict__ Yf,
                     __nv_bfloat16* __restrict__ Yhi,
                     __nv_bfloat16* __restrict__ Ylo,
                     float scale)
{
    extern __shared__ char smem[];
    const uint32_t sb = smem_u32(smem);
    const int tid = threadIdx.x;
    const int lane = tid & 31;
    const int wid = tid >> 5;
    const int warp_m = wid >> 2;
    const int warp_n = wid & 3;
    const int m0 = blockIdx.y * 128;
    const int n0 = blockIdx.x * 128;

    float acc[4][4][4];
#pragma unroll
    for (int a = 0; a < 4; a++)
#pragma unroll
        for (int b = 0; b < 4; b++)
#pragma unroll
            for (int c = 0; c < 4; c++) acc[a][b][c] = 0.f;

    auto prefetch = [&](int c, int stage) {
        const uint32_t sbase = sb + stage * STAGE_B;
        const int k0 = c * 32;
#pragma unroll
        for (int j = 0; j < 2; j++) {
            const int idx = j * 256 + tid;
            const int r  = (idx & 7) + (idx >> 5) * 8;
            const int ch = (idx >> 3) & 3;
            const uint32_t so = (uint32_t)(r * PITCH + ch * 16);
            const char* ga_hi = (const char*)(Ahi + (size_t)(m0 + r) * KDIM + k0) + ch * 16;
            const char* ga_lo = (const char*)(Alo + (size_t)(m0 + r) * KDIM + k0) + ch * 16;
            const char* gb_hi = (const char*)(Whi + (size_t)(n0 + r) * KDIM + k0) + ch * 16;
            const char* gb_lo = (const char*)(Wlo + (size_t)(n0 + r) * KDIM + k0) + ch * 16;
            CP16(sbase + so,           ga_hi);
            CP16(sbase + TSZ + so,     ga_lo);
            CP16(sbase + 2 * TSZ + so, gb_hi);
            CP16(sbase + 3 * TSZ + so, gb_lo);
        }
    };

    prefetch(0, 0); CP_COMMIT();
    prefetch(1, 1); CP_COMMIT();

    int stage = 0;
    for (int c = 0; c < NCH; c++) {
        CP_WAIT1();
        __syncthreads();
        const uint32_t sbase = sb + stage * STAGE_B;

#pragma unroll
        for (int s = 0; s < 2; s++) {
            uint32_t ah[4][4], al[4][4], bh[4][2], bl[4][2];
            const int lr = lane & 15;
            const int lh = lane >> 4;
#pragma unroll
            for (int mt = 0; mt < 4; mt++) {
                const uint32_t ad = sbase +
                    (uint32_t)((warp_m * 64 + mt * 16 + lr) * PITCH + s * 32 + lh * 16);
                LDSM_X4(ah[mt][0], ah[mt][1], ah[mt][2], ah[mt][3], ad);
                LDSM_X4(al[mt][0], al[mt][1], al[mt][2], al[mt][3], ad + TSZ);
            }
            const int br = (lane & 7) + ((lane >> 4) & 1) * 8;
            const int bk = ((lane >> 3) & 1) * 16;
#pragma unroll
            for (int np = 0; np < 2; np++) {
                const uint32_t bd = sbase + 2 * TSZ +
                    (uint32_t)((warp_n * 32 + np * 16 + br) * PITCH + s * 32 + bk);
                uint32_t t0, t1, t2, t3;
                LDSM_X4(t0, t1, t2, t3, bd);
                bh[np * 2][0] = t0; bh[np * 2][1] = t1;
                bh[np * 2 + 1][0] = t2; bh[np * 2 + 1][1] = t3;
                LDSM_X4(t0, t1, t2, t3, bd + TSZ);
                bl[np * 2][0] = t0; bl[np * 2][1] = t1;
                bl[np * 2 + 1][0] = t2; bl[np * 2 + 1][1] = t3;
            }
#pragma unroll
            for (int mt = 0; mt < 4; mt++) {
#pragma unroll
                for (int nt = 0; nt < 4; nt++) {
                    MMA_BF16(acc[mt][nt], ah[mt], bh[nt][0], bh[nt][1]);
                    MMA_BF16(acc[mt][nt], ah[mt], bl[nt][0], bl[nt][1]);
                    MMA_BF16(acc[mt][nt], al[mt], bh[nt][0], bh[nt][1]);
                }
            }
        }
        // prefetch distance 2: writes stage read at iteration c-1 (barrier-protected)
        if (c + 2 < NCH) {
            int ps = stage + 2; if (ps >= 3) ps -= 3;
            prefetch(c + 2, ps);
        }
        CP_COMMIT();
        if (++stage == 3) stage = 0;
    }

    const int gr = lane >> 2;
    const int gc = (lane & 3) * 2;
    const int row0 = m0 + warp_m * 64;
    const int col0 = n0 + warp_n * 32;
#pragma unroll
    for (int mt = 0; mt < 4; mt++) {
#pragma unroll
        for (int nt = 0; nt < 4; nt++) {
            const int r0 = row0 + mt * 16 + gr;
            const int cc = col0 + nt * 8 + gc;
            if (BF16OUT) {
                uint32_t hp, lp;
                split_pack(acc[mt][nt][0] * scale, acc[mt][nt][1] * scale, hp, lp);
                *reinterpret_cast<uint32_t*>(Yhi + (size_t)r0 * KDIM + cc) = hp;
                *reinterpret_cast<uint32_t*>(Ylo + (size_t)r0 * KDIM + cc) = lp;
                split_pack(acc[mt][nt][2] * scale, acc[mt][nt][3] * scale, hp, lp);
                *reinterpret_cast<uint32_t*>(Yhi + (size_t)(r0 + 8) * KDIM + cc) = hp;
                *reinterpret_cast<uint32_t*>(Ylo + (size_t)(r0 + 8) * KDIM + cc) = lp;
            } else {
                float* p0 = Yf + (size_t)r0 * KDIM + cc;
                float* p1 = p0 + 8 * KDIM;
                asm volatile("st.global.v2.f32 [%0], {%1, %2};"
                    :: "l"(p0), "f"(acc[mt][nt][0]), "f"(acc[mt][nt][1]) : "memory");
                asm volatile("st.global.v2.f32 [%0], {%1, %2};"
                    :: "l"(p1), "f"(acc[mt][nt][2]), "f"(acc[mt][nt][3]) : "memory");
            }
        }
    }
}

// ---------------------------------------------------------------------------
// HMMA flash attention (causal), split-bf16, log2-domain softmax.
// CTA: 128 q-rows (8 warps x 16), kv-tiles of 64, dh=64.
// 3-stage kv ring, prefetch distance 2, one barrier per iteration.
// ---------------------------------------------------------------------------
#define APITCH 144
#define AQT (128 * APITCH)       // 18432
#define AKT (64 * APITCH)        // 9216
#define ASTG (4 * AKT)           // 36864
#define ATTN_SMEM (2 * AQT + 3 * ASTG)   // 147456

__global__ __launch_bounds__(256, 1)
void attn_mma_kernel(const __nv_bfloat16* __restrict__ Qhi,
                     const __nv_bfloat16* __restrict__ Qlo,
                     const __nv_bfloat16* __restrict__ Khi,
                     const __nv_bfloat16* __restrict__ Klo,
                     const __nv_bfloat16* __restrict__ Vhi,
                     const __nv_bfloat16* __restrict__ Vlo,
                     __nv_bfloat16* __restrict__ Ohi,
                     __nv_bfloat16* __restrict__ Olo)
{
    extern __shared__ char smem[];
    const uint32_t sb = smem_u32(smem);
    const int tid = threadIdx.x;
    const int lane = tid & 31;
    const int wid = tid >> 5;
    const int mq = (L / 128 - 1) - blockIdx.x;     // heavy tiles first
    const int bh = blockIdx.y;
    const int b = bh >> 4;
    const int h = bh & 15;
    const int m0 = mq * 128;
    const int ntiles = mq * 2 + 2;

    const size_t qg = ((size_t)b * L + m0) * D + h * DH;
    const size_t kg = (size_t)b * S * D + h * DH;

    // Q prefetch (part of group 0)
#pragma unroll
    for (int i = 0; i < 8; i++) {
        const int idx = i * 256 + tid;
        const int tsr = idx >> 10;
        const int rem = idx & 1023;
        const int row = rem >> 3;
        const int ch = rem & 7;
        const __nv_bfloat16* src = (tsr ? Qlo : Qhi) + qg + (size_t)row * D + ch * 8;
        CP16(sb + tsr * AQT + row * APITCH + ch * 16, src);
    }

    auto prefetch_kv = [&](int j, int stage) {
        const int n0 = j * 64;
#pragma unroll
        for (int i = 0; i < 8; i++) {
            const int idx = i * 256 + tid;
            const int tsr = idx >> 9;
            const int rem = idx & 511;
            const int row = rem >> 3;
            const int ch = rem & 7;
            const __nv_bfloat16* base =
                (tsr == 0) ? Khi : (tsr == 1) ? Klo : (tsr == 2) ? Vhi : Vlo;
            const __nv_bfloat16* src = base + kg + (size_t)(n0 + row) * D + ch * 8;
            CP16(sb + 2 * AQT + stage * ASTG + tsr * AKT + row * APITCH + ch * 16, src);
        }
    };

    prefetch_kv(0, 0); CP_COMMIT();
    if (1 < ntiles) prefetch_kv(1, 1);
    CP_COMMIT();

    float oacc[8][4];
#pragma unroll
    for (int j = 0; j < 8; j++)
#pragma unroll
        for (int e = 0; e < 4; e++) oacc[j][e] = 0.f;

    float m1 = -INFINITY, m2 = -INFINITY, l1 = 0.f, l2 = 0.f;
    uint32_t qh[4][4], ql[4][4];

    const int lr = lane & 15;
    const int lh = lane >> 4;
    const int br = (lane & 7) + ((lane >> 4) & 1) * 8;
    const int bk = ((lane >> 3) & 1) * 16;
    const int vs_off = ((lane >> 3) & 1) * 8 + (lane & 7);
    const int vdb = (lane >> 4) * 16;
    const int qbw = m0 + wid * 16;

    int stage = 0;
    for (int jt = 0; jt < ntiles; jt++) {
        CP_WAIT1();
        __syncthreads();
        const uint32_t kbase = sb + 2 * AQT + stage * ASTG;
        const uint32_t vbase = kbase + 2 * AKT;

        if (jt == 0) {
#pragma unroll
            for (int ks = 0; ks < 4; ks++) {
                const uint32_t ad = sb +
                    (uint32_t)((wid * 16 + lr) * APITCH + ks * 32 + lh * 16);
                LDSM_X4(qh[ks][0], qh[ks][1], qh[ks][2], qh[ks][3], ad);
                LDSM_X4(ql[ks][0], ql[ks][1], ql[ks][2], ql[ks][3], ad + AQT);
            }
        }

        // ---- S = Q K^T ----
        float sacc[8][4];
#pragma unroll
        for (int j = 0; j < 8; j++)
#pragma unroll
            for (int e = 0; e < 4; e++) sacc[j][e] = 0.f;

#pragma unroll
        for (int ks = 0; ks < 4; ks++) {
#pragma unroll
            for (int np = 0; np < 4; np++) {
                const uint32_t bd = kbase +
                    (uint32_t)((np * 16 + br) * APITCH + ks * 32 + bk);
                uint32_t t0, t1, t2, t3, u0, u1, u2, u3;
                LDSM_X4(t0, t1, t2, t3, bd);
                LDSM_X4(u0, u1, u2, u3, bd + AKT);
                MMA_BF16(sacc[np * 2], qh[ks], t0, t1);
                MMA_BF16(sacc[np * 2], qh[ks], u0, u1);
                MMA_BF16(sacc[np * 2], ql[ks], t0, t1);
                MMA_BF16(sacc[np * 2 + 1], qh[ks], t2, t3);
                MMA_BF16(sacc[np * 2 + 1], qh[ks], u2, u3);
                MMA_BF16(sacc[np * 2 + 1], ql[ks], t2, t3);
            }
        }

        // ---- causal mask (near-diagonal tiles only) ----
        const int n0 = jt * 64;
        if (n0 + 63 > qbw) {
            const int r1 = qbw + (lane >> 2);
            const int r2 = r1 + 8;
#pragma unroll
            for (int j = 0; j < 8; j++) {
                const int c0 = n0 + j * 8 + (lane & 3) * 2;
                if (c0 > r1) sacc[j][0] = -INFINITY;
                if (c0 + 1 > r1) sacc[j][1] = -INFINITY;
                if (c0 > r2) sacc[j][2] = -INFINITY;
                if (c0 + 1 > r2) sacc[j][3] = -INFINITY;
            }
        }

        // ---- online softmax (log2 domain) ----
        float mt1 = -INFINITY, mt2 = -INFINITY;
#pragma unroll
        for (int j = 0; j < 8; j++) {
            mt1 = fmaxf(mt1, fmaxf(sacc[j][0], sacc[j][1]));
            mt2 = fmaxf(mt2, fmaxf(sacc[j][2], sacc[j][3]));
        }
        mt1 = fmaxf(mt1, __shfl_xor_sync(0xFFFFFFFFu, mt1, 1));
        mt1 = fmaxf(mt1, __shfl_xor_sync(0xFFFFFFFFu, mt1, 2));
        mt2 = fmaxf(mt2, __shfl_xor_sync(0xFFFFFFFFu, mt2, 1));
        mt2 = fmaxf(mt2, __shfl_xor_sync(0xFFFFFFFFu, mt2, 2));

        const float nm1 = fmaxf(m1, mt1);
        const float nm2 = fmaxf(m2, mt2);
        const float f1 = ex2f(m1 - nm1);
        const float f2 = ex2f(m2 - nm2);
        m1 = nm1; m2 = nm2;

        float rs1 = 0.f, rs2 = 0.f;
#pragma unroll
        for (int j = 0; j < 8; j++) {
            sacc[j][0] = ex2f(sacc[j][0] - nm1);
            sacc[j][1] = ex2f(sacc[j][1] - nm1);
            sacc[j][2] = ex2f(sacc[j][2] - nm2);
            sacc[j][3] = ex2f(sacc[j][3] - nm2);
            rs1 += sacc[j][0] + sacc[j][1];
            rs2 += sacc[j][2] + sacc[j][3];
        }
        rs1 += __shfl_xor_sync(0xFFFFFFFFu, rs1, 1);
        rs1 += __shfl_xor_sync(0xFFFFFFFFu, rs1, 2);
        rs2 += __shfl_xor_sync(0xFFFFFFFFu, rs2, 1);
        rs2 += __shfl_xor_sync(0xFFFFFFFFu, rs2, 2);
        l1 = l1 * f1 + rs1;
        l2 = l2 * f2 + rs2;

#pragma unroll
        for (int j = 0; j < 8; j++) {
            oacc[j][0] *= f1; oacc[j][1] *= f1;
            oacc[j][2] *= f2; oacc[j][3] *= f2;
        }

        // ---- O += P V ----
#pragma unroll
        for (int t = 0; t < 4; t++) {
            uint32_t ph[4], pl[4];
            split_pack(sacc[2 * t][0], sacc[2 * t][1], ph[0], pl[0]);
            split_pack(sacc[2 * t][2], sacc[2 * t][3], ph[1], pl[1]);
            split_pack(sacc[2 * t + 1][0], sacc[2 * t + 1][1], ph[2], pl[2]);
            split_pack(sacc[2 * t + 1][2], sacc[2 * t + 1][3], ph[3], pl[3]);
#pragma unroll
            for (int dp = 0; dp < 4; dp++) {
                const uint32_t vd = vbase +
                    (uint32_t)((t * 16 + vs_off) * APITCH + vdb + dp * 32);
                uint32_t t0, t1, t2, t3, u0, u1, u2, u3;
                LDSM_X4_T(t0, t1, t2, t3, vd);
                LDSM_X4_T(u0, u1, u2, u3, vd + AKT);
                MMA_BF16(oacc[dp * 2], ph, t0, t1);
                MMA_BF16(oacc[dp * 2], ph, u0, u1);
                MMA_BF16(oacc[dp * 2], pl, t0, t1);
                MMA_BF16(oacc[dp * 2 + 1], ph, t2, t3);
                MMA_BF16(oacc[dp * 2 + 1], ph, u2, u3);
                MMA_BF16(oacc[dp * 2 + 1], pl, t2, t3);
            }
        }

        // prefetch distance 2 (stage read last iteration; barrier-protected)
        if (jt + 2 < ntiles) {
            int ps = stage + 2; if (ps >= 3) ps -= 3;
            prefetch_kv(jt + 2, ps);
        }
        CP_COMMIT();
        if (++stage == 3) stage = 0;
    }

    // ---- epilogue ----
    const float inv1 = 1.f / l1;
    const float inv2 = 1.f / l2;
    const int r1 = m0 + wid * 16 + (lane >> 2);
    const int r2 = r1 + 8;
    const int cbase = h * DH + (lane & 3) * 2;
#pragma unroll
    for (int j = 0; j < 8; j++) {
        const int cc = cbase + j * 8;
        uint32_t hp, lp;
        split_pack(oacc[j][0] * inv1, oacc[j][1] * inv1, hp, lp);
        *reinterpret_cast<uint32_t*>(Ohi + ((size_t)b * L + r1) * D + cc) = hp;
        *reinterpret_cast<uint32_t*>(Olo + ((size_t)b * L + r1) * D + cc) = lp;
        split_pack(oacc[j][2] * inv2, oacc[j][3] * inv2, hp, lp);
        *reinterpret_cast<uint32_t*>(Ohi + ((size_t)b * L + r2) * D + cc) = hp;
        *reinterpret_cast<uint32_t*>(Olo + ((size_t)b * L + r2) * D + cc) = lp;
    }
}

// ---------------------------------------------------------------------------
// Launch
// ---------------------------------------------------------------------------
extern "C" void kernel_launch(void* const* d_in, const int* in_sizes, int n_in,
                              void* d_out, int out_size)
{
    const float* q_in = (const float*)d_in[0];
    const float* k_in = (const float*)d_in[1];
    const float* v_in = (const float*)d_in[2];
    const float* Wq   = (const float*)d_in[3];
    const float* Wk   = (const float*)d_in[4];
    const float* Wv   = (const float*)d_in[5];
    const float* Wo   = (const float*)d_in[6];
    float* out = (float*)d_out;

    __nv_bfloat16 *ainh, *ainl, *binh, *binl, *cinh, *cinl;
    __nv_bfloat16 *wqh, *wql, *wkh, *wkl, *wvh, *wvl, *woh, *wol;
    __nv_bfloat16 *qh, *qlp, *kh, *kl, *vh, *vl, *oh, *ol;
    cudaGetSymbolAddress((void**)&ainh, g_ain_hi);
    cudaGetSymbolAddress((void**)&ainl, g_ain_lo);
    cudaGetSymbolAddress((void**)&binh, g_bin_hi);
    cudaGetSymbolAddress((void**)&binl, g_bin_lo);
    cudaGetSymbolAddress((void**)&cinh, g_cin_hi);
    cudaGetSymbolAddress((void**)&cinl, g_cin_lo);
    cudaGetSymbolAddress((void**)&wqh, g_wq_hi);
    cudaGetSymbolAddress((void**)&wql, g_wq_lo);
    cudaGetSymbolAddress((void**)&wkh, g_wk_hi);
    cudaGetSymbolAddress((void**)&wkl, g_wk_lo);
    cudaGetSymbolAddress((void**)&wvh, g_wv_hi);
    cudaGetSymbolAddress((void**)&wvl, g_wv_lo);
    cudaGetSymbolAddress((void**)&woh, g_wo_hi);
    cudaGetSymbolAddress((void**)&wol, g_wo_lo);
    cudaGetSymbolAddress((void**)&qh, g_q_hi);
    cudaGetSymbolAddress((void**)&qlp, g_q_lo);
    cudaGetSymbolAddress((void**)&kh, g_k_hi);
    cudaGetSymbolAddress((void**)&kl, g_k_lo);
    cudaGetSymbolAddress((void**)&vh, g_v_hi);
    cudaGetSymbolAddress((void**)&vl, g_v_lo);
    cudaGetSymbolAddress((void**)&oh, g_o_hi);
    cudaGetSymbolAddress((void**)&ol, g_o_lo);

    cudaFuncSetAttribute(gemm_mma_kernel<true>,
                         cudaFuncAttributeMaxDynamicSharedMemorySize, GEMM_SMEM);
    cudaFuncSetAttribute(gemm_mma_kernel<false>,
                         cudaFuncAttributeMaxDynamicSharedMemorySize, GEMM_SMEM);
    cudaFuncSetAttribute(attn_mma_kernel,
                         cudaFuncAttributeMaxDynamicSharedMemorySize, ATTN_SMEM);

    const int Nrows = B * L;
    const int nInp4 = Nrows * D / 4;
    const int nW4   = D * D / 4;

    dim3 wgrid((nW4 + 255) / 256, 4);
    split_w4_kernel<<<wgrid, 256>>>(Wq, Wk, Wv, Wo);
    dim3 igrid((nInp4 + 255) / 256, 3);
    split_in3_kernel<<<igrid, 256>>>(q_in, k_in, v_in);

    dim3 ggrid(D / 128, Nrows / 128);
    const float qscale = 0.125f * 1.4426950408889634f;   // fold 1/sqrt(dh) * log2(e)
    gemm_mma_kernel<true><<<ggrid, 256, GEMM_SMEM>>>(ainh, ainl, wqh, wql,
                                                     nullptr, qh, qlp, qscale);
    gemm_mma_kernel<true><<<ggrid, 256, GEMM_SMEM>>>(binh, binl, wkh, wkl,
                                                     nullptr, kh, kl, 1.f);
    gemm_mma_kernel<true><<<ggrid, 256, GEMM_SMEM>>>(cinh, cinl, wvh, wvl,
                                                     nullptr, vh, vl, 1.f);

    dim3 agrid(L / 128, B * H);
    attn_mma_kernel<<<agrid, 256, ATTN_SMEM>>>(qh, qlp, kh, kl, vh, vl, oh, ol);

    gemm_mma_kernel<false><<<ggrid, 256, GEMM_SMEM>>>(oh, ol, woh, wol,
                                                      out, nullptr, nullptr, 1.f);
}

// round 12
// speedup vs baseline: 3.1193x; 1.0222x over previous
#include <cuda_runtime.h>
#include <cuda_bf16.h>
#include <math.h>
#include <stdint.h>

// Problem constants
#define B 4
#define L 2048
#define S 2048
#define D 1024
#define H 16
#define DH 64

// ---------------------------------------------------------------------------
// Scratch (device globals — no allocation allowed)
// ---------------------------------------------------------------------------
__device__ __nv_bfloat16 g_ain_hi[B * L * D];
__device__ __nv_bfloat16 g_ain_lo[B * L * D];
__device__ __nv_bfloat16 g_bin_hi[B * L * D];
__device__ __nv_bfloat16 g_bin_lo[B * L * D];
__device__ __nv_bfloat16 g_cin_hi[B * L * D];
__device__ __nv_bfloat16 g_cin_lo[B * L * D];
__device__ __nv_bfloat16 g_wq_hi[D * D];
__device__ __nv_bfloat16 g_wq_lo[D * D];
__device__ __nv_bfloat16 g_wk_hi[D * D];
__device__ __nv_bfloat16 g_wk_lo[D * D];
__device__ __nv_bfloat16 g_wv_hi[D * D];
__device__ __nv_bfloat16 g_wv_lo[D * D];
__device__ __nv_bfloat16 g_wo_hi[D * D];
__device__ __nv_bfloat16 g_wo_lo[D * D];
__device__ __nv_bfloat16 g_q_hi[B * L * D];
__device__ __nv_bfloat16 g_q_lo[B * L * D];
__device__ __nv_bfloat16 g_k_hi[B * S * D];
__device__ __nv_bfloat16 g_k_lo[B * S * D];
__device__ __nv_bfloat16 g_v_hi[B * S * D];
__device__ __nv_bfloat16 g_v_lo[B * S * D];
__device__ __nv_bfloat16 g_o_hi[B * L * D];
__device__ __nv_bfloat16 g_o_lo[B * L * D];

// ---------------------------------------------------------------------------
// Helpers (baseline compute_103-safe PTX only)
// ---------------------------------------------------------------------------
__device__ __forceinline__ uint32_t smem_u32(const void* p) {
    uint32_t a;
    asm("{ .reg .u64 t; cvta.to.shared.u64 t, %1; cvt.u32.u64 %0, t; }"
        : "=r"(a) : "l"(p));
    return a;
}

#define CP16(dst, src) \
    asm volatile("cp.async.cg.shared.global [%0], [%1], 16;" \
        :: "r"(dst), "l"(src) : "memory")

#define CP_COMMIT() asm volatile("cp.async.commit_group;" ::: "memory")
#define CP_WAIT1()  asm volatile("cp.async.wait_group 1;" ::: "memory")

#define LDSM_X4(r0, r1, r2, r3, addr) \
    asm volatile("ldmatrix.sync.aligned.m8n8.x4.shared.b16 {%0,%1,%2,%3}, [%4];" \
        : "=r"(r0), "=r"(r1), "=r"(r2), "=r"(r3) : "r"(addr))

#define LDSM_X4_T(r0, r1, r2, r3, addr) \
    asm volatile("ldmatrix.sync.aligned.m8n8.x4.trans.shared.b16 {%0,%1,%2,%3}, [%4];" \
        : "=r"(r0), "=r"(r1), "=r"(r2), "=r"(r3) : "r"(addr))

#define MMA_BF16(c, a, b0, b1) \
    asm volatile("mma.sync.aligned.m16n8k16.row.col.f32.bf16.bf16.f32 " \
        "{%0,%1,%2,%3}, {%4,%5,%6,%7}, {%8,%9}, {%0,%1,%2,%3};" \
        : "+f"((c)[0]), "+f"((c)[1]), "+f"((c)[2]), "+f"((c)[3]) \
        : "r"((a)[0]), "r"((a)[1]), "r"((a)[2]), "r"((a)[3]), \
          "r"(b0), "r"(b1))

__device__ __forceinline__ float ex2f(float x) {
    float r;
    asm("ex2.approx.f32 %0, %1;" : "=f"(r) : "f"(x));
    return r;
}

__device__ __forceinline__ uint32_t pack_bf16x2(float lo, float hi) {
    uint32_t r;
    asm("cvt.rn.bf16x2.f32 %0, %1, %2;" : "=r"(r) : "f"(hi), "f"(lo));
    return r;
}

__device__ __forceinline__ void split_pack(float v0, float v1,
                                           uint32_t& hp, uint32_t& lp) {
    __nv_bfloat16 h0 = __float2bfloat16(v0);
    __nv_bfloat16 h1 = __float2bfloat16(v1);
    __nv_bfloat162 hh(h0, h1);
    hp = *reinterpret_cast<uint32_t*>(&hh);
    lp = pack_bf16x2(v0 - __bfloat162float(h0), v1 - __bfloat162float(h1));
}

// ---------------------------------------------------------------------------
// Split kernels (merged: weights x4, inputs x3)
// ---------------------------------------------------------------------------
__device__ __forceinline__ void split_body(const float* __restrict__ x,
                                           __nv_bfloat16* __restrict__ hi,
                                           __nv_bfloat16* __restrict__ lo, int n4)
{
    int i = blockIdx.x * blockDim.x + threadIdx.x;
    if (i >= n4) return;
    float4 v = reinterpret_cast<const float4*>(x)[i];
    uint2 hv, lv;
    split_pack(v.x, v.y, hv.x, lv.x);
    split_pack(v.z, v.w, hv.y, lv.y);
    reinterpret_cast<uint2*>(hi)[i] = hv;
    reinterpret_cast<uint2*>(lo)[i] = lv;
}

__global__ __launch_bounds__(256)
void split_w4_kernel(const float* __restrict__ Wq, const float* __restrict__ Wk,
                     const float* __restrict__ Wv, const float* __restrict__ Wo)
{
    const int seg = blockIdx.y;
    const float* src = (seg == 0) ? Wq : (seg == 1) ? Wk : (seg == 2) ? Wv : Wo;
    __nv_bfloat16* hi = (seg == 0) ? g_wq_hi : (seg == 1) ? g_wk_hi
                       : (seg == 2) ? g_wv_hi : g_wo_hi;
    __nv_bfloat16* lo = (seg == 0) ? g_wq_lo : (seg == 1) ? g_wk_lo
                       : (seg == 2) ? g_wv_lo : g_wo_lo;
    split_body(src, hi, lo, D * D / 4);
}

__global__ __launch_bounds__(256)
void split_in3_kernel(const float* __restrict__ q, const float* __restrict__ k,
                      const float* __restrict__ v)
{
    const int seg = blockIdx.y;
    const float* src = (seg == 0) ? q : (seg == 1) ? k : v;
    __nv_bfloat16* hi = (seg == 0) ? g_ain_hi : (seg == 1) ? g_bin_hi : g_cin_hi;
    __nv_bfloat16* lo = (seg == 0) ? g_ain_lo : (seg == 1) ? g_bin_lo : g_cin_lo;
    split_body(src, hi, lo, B * L * D / 4);
}

// ---------------------------------------------------------------------------
// HMMA split-bf16 GEMM:  Y[m, n] = sum_k A[m,k] * W[n,k]
// CTA tile 128x256, warp tile 64x64 (8 warps as 2x4), k-chunk 32.
// 3-stage cp.async ring, prefetch distance 2, one barrier per iteration.
// ---------------------------------------------------------------------------
#define KDIM 1024
#define NCH 32
#define PITCH 80
#define ATSZ (128 * PITCH)          // 10240
#define BTSZ (256 * PITCH)          // 20480
#define STAGE_B (2 * ATSZ + 2 * BTSZ)   // 61440
#define GEMM_SMEM (3 * STAGE_B)     // 184320

template<bool BF16OUT>
__global__ __launch_bounds__(256, 1)
void gemm_mma_kernel(const __nv_bfloat16* __restrict__ Ahi,
                     const __nv_bfloat16* __restrict__ Alo,
                     const __nv_bfloat16* __restrict__ Whi,
                     const __nv_bfloat16* __restrict__ Wlo,
                     float* __restrict__ Yf,
                     __nv_bfloat16* __restrict__ Yhi,
                     __nv_bfloat16* __restrict__ Ylo,
                     float scale)
{
    extern __shared__ char smem[];
    const uint32_t sb = smem_u32(smem);
    const int tid = threadIdx.x;
    const int lane = tid & 31;
    const int wid = tid >> 5;
    const int warp_m = wid >> 2;      // 0..1 (64-row slab)
    const int warp_n = wid & 3;       // 0..3 (64-col slab)
    const int m0 = blockIdx.y * 128;
    const int n0 = blockIdx.x * 256;

    float acc[4][8][4];
#pragma unroll
    for (int a = 0; a < 4; a++)
#pragma unroll
        for (int b = 0; b < 8; b++)
#pragma unroll
            for (int c = 0; c < 4; c++) acc[a][b][c] = 0.f;

    auto prefetch = [&](int c, int stage) {
        const uint32_t sbase = sb + stage * STAGE_B;
        const int k0 = c * 32;
#pragma unroll
        for (int j = 0; j < 12; j++) {
            const int idx = j * 256 + tid;
            if (idx < 1024) {
                const int half = idx >> 9;            // 0 hi, 1 lo
                const int rem = idx & 511;
                const int r = rem >> 2, ch = rem & 3;
                const __nv_bfloat16* src = (half ? Alo : Ahi)
                    + (size_t)(m0 + r) * KDIM + k0 + ch * 8;
                CP16(sbase + half * ATSZ + r * PITCH + ch * 16, src);
            } else {
                const int bidx = idx - 1024;
                const int half = bidx >> 10;          // 0 hi, 1 lo
                const int rem = bidx & 1023;
                const int r = rem >> 2, ch = rem & 3;
                const __nv_bfloat16* src = (half ? Wlo : Whi)
                    + (size_t)(n0 + r) * KDIM + k0 + ch * 8;
                CP16(sbase + 2 * ATSZ + half * BTSZ + r * PITCH + ch * 16, src);
            }
        }
    };

    prefetch(0, 0); CP_COMMIT();
    prefetch(1, 1); CP_COMMIT();

    const int lr = lane & 15;
    const int lh = lane >> 4;
    const int br = (lane & 7) + ((lane >> 4) & 1) * 8;
    const int bk = ((lane >> 3) & 1) * 16;

    int stage = 0;
    for (int c = 0; c < NCH; c++) {
        CP_WAIT1();
        __syncthreads();
        const uint32_t sbase = sb + stage * STAGE_B;
        const uint32_t bbase = sbase + 2 * ATSZ;

#pragma unroll
        for (int s = 0; s < 2; s++) {
            uint32_t ah[4][4], al[4][4];
#pragma unroll
            for (int mt = 0; mt < 4; mt++) {
                const uint32_t ad = sbase +
                    (uint32_t)((warp_m * 64 + mt * 16 + lr) * PITCH + s * 32 + lh * 16);
                LDSM_X4(ah[mt][0], ah[mt][1], ah[mt][2], ah[mt][3], ad);
                LDSM_X4(al[mt][0], al[mt][1], al[mt][2], al[mt][3], ad + ATSZ);
            }
#pragma unroll
            for (int np = 0; np < 4; np++) {
                const uint32_t bd = bbase +
                    (uint32_t)((warp_n * 64 + np * 16 + br) * PITCH + s * 32 + bk);
                uint32_t t0, t1, t2, t3, u0, u1, u2, u3;
                LDSM_X4(t0, t1, t2, t3, bd);
                LDSM_X4(u0, u1, u2, u3, bd + BTSZ);
#pragma unroll
                for (int mt = 0; mt < 4; mt++) {
                    MMA_BF16(acc[mt][np * 2], ah[mt], t0, t1);
                    MMA_BF16(acc[mt][np * 2], ah[mt], u0, u1);
                    MMA_BF16(acc[mt][np * 2], al[mt], t0, t1);
                    MMA_BF16(acc[mt][np * 2 + 1], ah[mt], t2, t3);
                    MMA_BF16(acc[mt][np * 2 + 1], ah[mt], u2, u3);
                    MMA_BF16(acc[mt][np * 2 + 1], al[mt], t2, t3);
                }
            }
        }
        if (c + 2 < NCH) {
            int ps = stage + 2; if (ps >= 3) ps -= 3;
            prefetch(c + 2, ps);
        }
        CP_COMMIT();
        if (++stage == 3) stage = 0;
    }

    const int gr = lane >> 2;
    const int gc = (lane & 3) * 2;
    const int row0 = m0 + warp_m * 64;
    const int col0 = n0 + warp_n * 64;
#pragma unroll
    for (int mt = 0; mt < 4; mt++) {
#pragma unroll
        for (int nt = 0; nt < 8; nt++) {
            const int r0 = row0 + mt * 16 + gr;
            const int cc = col0 + nt * 8 + gc;
            if (BF16OUT) {
                uint32_t hp, lp;
                split_pack(acc[mt][nt][0] * scale, acc[mt][nt][1] * scale, hp, lp);
                *reinterpret_cast<uint32_t*>(Yhi + (size_t)r0 * KDIM + cc) = hp;
                *reinterpret_cast<uint32_t*>(Ylo + (size_t)r0 * KDIM + cc) = lp;
                split_pack(acc[mt][nt][2] * scale, acc[mt][nt][3] * scale, hp, lp);
                *reinterpret_cast<uint32_t*>(Yhi + (size_t)(r0 + 8) * KDIM + cc) = hp;
                *reinterpret_cast<uint32_t*>(Ylo + (size_t)(r0 + 8) * KDIM + cc) = lp;
            } else {
                float* p0 = Yf + (size_t)r0 * KDIM + cc;
                float* p1 = p0 + 8 * KDIM;
                asm volatile("st.global.v2.f32 [%0], {%1, %2};"
                    :: "l"(p0), "f"(acc[mt][nt][0]), "f"(acc[mt][nt][1]) : "memory");
                asm volatile("st.global.v2.f32 [%0], {%1, %2};"
                    :: "l"(p1), "f"(acc[mt][nt][2]), "f"(acc[mt][nt][3]) : "memory");
            }
        }
    }
}

// ---------------------------------------------------------------------------
// HMMA flash attention (causal), split-bf16, log2-domain softmax. (unchanged)
// CTA: 128 q-rows (8 warps x 16), kv-tiles of 64, dh=64.
// ---------------------------------------------------------------------------
#define APITCH 144
#define AQT (128 * APITCH)
#define AKT (64 * APITCH)
#define ASTG (4 * AKT)
#define ATTN_SMEM (2 * AQT + 3 * ASTG)   // 147456

__global__ __launch_bounds__(256, 1)
void attn_mma_kernel(const __nv_bfloat16* __restrict__ Qhi,
                     const __nv_bfloat16* __restrict__ Qlo,
                     const __nv_bfloat16* __restrict__ Khi,
                     const __nv_bfloat16* __restrict__ Klo,
                     const __nv_bfloat16* __restrict__ Vhi,
                     const __nv_bfloat16* __restrict__ Vlo,
                     __nv_bfloat16* __restrict__ Ohi,
                     __nv_bfloat16* __restrict__ Olo)
{
    extern __shared__ char smem[];
    const uint32_t sb = smem_u32(smem);
    const int tid = threadIdx.x;
    const int lane = tid & 31;
    const int wid = tid >> 5;
    const int mq = (L / 128 - 1) - blockIdx.x;
    const int bh = blockIdx.y;
    const int b = bh >> 4;
    const int h = bh & 15;
    const int m0 = mq * 128;
    const int ntiles = mq * 2 + 2;

    const size_t qg = ((size_t)b * L + m0) * D + h * DH;
    const size_t kg = (size_t)b * S * D + h * DH;

#pragma unroll
    for (int i = 0; i < 8; i++) {
        const int idx = i * 256 + tid;
        const int tsr = idx >> 10;
        const int rem = idx & 1023;
        const int row = rem >> 3;
        const int ch = rem & 7;
        const __nv_bfloat16* src = (tsr ? Qlo : Qhi) + qg + (size_t)row * D + ch * 8;
        CP16(sb + tsr * AQT + row * APITCH + ch * 16, src);
    }

    auto prefetch_kv = [&](int j, int stage) {
        const int n0 = j * 64;
#pragma unroll
        for (int i = 0; i < 8; i++) {
            const int idx = i * 256 + tid;
            const int tsr = idx >> 9;
            const int rem = idx & 511;
            const int row = rem >> 3;
            const int ch = rem & 7;
            const __nv_bfloat16* base =
                (tsr == 0) ? Khi : (tsr == 1) ? Klo : (tsr == 2) ? Vhi : Vlo;
            const __nv_bfloat16* src = base + kg + (size_t)(n0 + row) * D + ch * 8;
            CP16(sb + 2 * AQT + stage * ASTG + tsr * AKT + row * APITCH + ch * 16, src);
        }
    };

    prefetch_kv(0, 0); CP_COMMIT();
    if (1 < ntiles) prefetch_kv(1, 1);
    CP_COMMIT();

    float oacc[8][4];
#pragma unroll
    for (int j = 0; j < 8; j++)
#pragma unroll
        for (int e = 0; e < 4; e++) oacc[j][e] = 0.f;

    float m1 = -INFINITY, m2 = -INFINITY, l1 = 0.f, l2 = 0.f;
    uint32_t qh[4][4], ql[4][4];

    const int lr = lane & 15;
    const int lh = lane >> 4;
    const int br = (lane & 7) + ((lane >> 4) & 1) * 8;
    const int bk = ((lane >> 3) & 1) * 16;
    const int vs_off = ((lane >> 3) & 1) * 8 + (lane & 7);
    const int vdb = (lane >> 4) * 16;
    const int qbw = m0 + wid * 16;

    int stage = 0;
    for (int jt = 0; jt < ntiles; jt++) {
        CP_WAIT1();
        __syncthreads();
        const uint32_t kbase = sb + 2 * AQT + stage * ASTG;
        const uint32_t vbase = kbase + 2 * AKT;

        if (jt == 0) {
#pragma unroll
            for (int ks = 0; ks < 4; ks++) {
                const uint32_t ad = sb +
                    (uint32_t)((wid * 16 + lr) * APITCH + ks * 32 + lh * 16);
                LDSM_X4(qh[ks][0], qh[ks][1], qh[ks][2], qh[ks][3], ad);
                LDSM_X4(ql[ks][0], ql[ks][1], ql[ks][2], ql[ks][3], ad + AQT);
            }
        }

        float sacc[8][4];
#pragma unroll
        for (int j = 0; j < 8; j++)
#pragma unroll
            for (int e = 0; e < 4; e++) sacc[j][e] = 0.f;

#pragma unroll
        for (int ks = 0; ks < 4; ks++) {
#pragma unroll
            for (int np = 0; np < 4; np++) {
                const uint32_t bd = kbase +
                    (uint32_t)((np * 16 + br) * APITCH + ks * 32 + bk);
                uint32_t t0, t1, t2, t3, u0, u1, u2, u3;
                LDSM_X4(t0, t1, t2, t3, bd);
                LDSM_X4(u0, u1, u2, u3, bd + AKT);
                MMA_BF16(sacc[np * 2], qh[ks], t0, t1);
                MMA_BF16(sacc[np * 2], qh[ks], u0, u1);
                MMA_BF16(sacc[np * 2], ql[ks], t0, t1);
                MMA_BF16(sacc[np * 2 + 1], qh[ks], t2, t3);
                MMA_BF16(sacc[np * 2 + 1], qh[ks], u2, u3);
                MMA_BF16(sacc[np * 2 + 1], ql[ks], t2, t3);
            }
        }

        const int n0 = jt * 64;
        if (n0 + 63 > qbw) {
            const int r1 = qbw + (lane >> 2);
            const int r2 = r1 + 8;
#pragma unroll
            for (int j = 0; j < 8; j++) {
                const int c0 = n0 + j * 8 + (lane & 3) * 2;
                if (c0 > r1) sacc[j][0] = -INFINITY;
                if (c0 + 1 > r1) sacc[j][1] = -INFINITY;
                if (c0 > r2) sacc[j][2] = -INFINITY;
                if (c0 + 1 > r2) sacc[j][3] = -INFINITY;
            }
        }

        float mt1 = -INFINITY, mt2 = -INFINITY;
#pragma unroll
        for (int j = 0; j < 8; j++) {
            mt1 = fmaxf(mt1, fmaxf(sacc[j][0], sacc[j][1]));
            mt2 = fmaxf(mt2, fmaxf(sacc[j][2], sacc[j][3]));
        }
        mt1 = fmaxf(mt1, __shfl_xor_sync(0xFFFFFFFFu, mt1, 1));
        mt1 = fmaxf(mt1, __shfl_xor_sync(0xFFFFFFFFu, mt1, 2));
        mt2 = fmaxf(mt2, __shfl_xor_sync(0xFFFFFFFFu, mt2, 1));
        mt2 = fmaxf(mt2, __shfl_xor_sync(0xFFFFFFFFu, mt2, 2));

        const float nm1 = fmaxf(m1, mt1);
        const float nm2 = fmaxf(m2, mt2);
        const float f1 = ex2f(m1 - nm1);
        const float f2 = ex2f(m2 - nm2);
        m1 = nm1; m2 = nm2;

        float rs1 = 0.f, rs2 = 0.f;
#pragma unroll
        for (int j = 0; j < 8; j++) {
            sacc[j][0] = ex2f(sacc[j][0] - nm1);
            sacc[j][1] = ex2f(sacc[j][1] - nm1);
            sacc[j][2] = ex2f(sacc[j][2] - nm2);
            sacc[j][3] = ex2f(sacc[j][3] - nm2);
            rs1 += sacc[j][0] + sacc[j][1];
            rs2 += sacc[j][2] + sacc[j][3];
        }
        rs1 += __shfl_xor_sync(0xFFFFFFFFu, rs1, 1);
        rs1 += __shfl_xor_sync(0xFFFFFFFFu, rs1, 2);
        rs2 += __shfl_xor_sync(0xFFFFFFFFu, rs2, 1);
        rs2 += __shfl_xor_sync(0xFFFFFFFFu, rs2, 2);
        l1 = l1 * f1 + rs1;
        l2 = l2 * f2 + rs2;

#pragma unroll
        for (int j = 0; j < 8; j++) {
            oacc[j][0] *= f1; oacc[j][1] *= f1;
            oacc[j][2] *= f2; oacc[j][3] *= f2;
        }

#pragma unroll
        for (int t = 0; t < 4; t++) {
            uint32_t ph[4], pl[4];
            split_pack(sacc[2 * t][0], sacc[2 * t][1], ph[0], pl[0]);
            split_pack(sacc[2 * t][2], sacc[2 * t][3], ph[1], pl[1]);
            split_pack(sacc[2 * t + 1][0], sacc[2 * t + 1][1], ph[2], pl[2]);
            split_pack(sacc[2 * t + 1][2], sacc[2 * t + 1][3], ph[3], pl[3]);
#pragma unroll
            for (int dp = 0; dp < 4; dp++) {
                const uint32_t vd = vbase +
                    (uint32_t)((t * 16 + vs_off) * APITCH + vdb + dp * 32);
                uint32_t t0, t1, t2, t3, u0, u1, u2, u3;
                LDSM_X4_T(t0, t1, t2, t3, vd);
                LDSM_X4_T(u0, u1, u2, u3, vd + AKT);
                MMA_BF16(oacc[dp * 2], ph, t0, t1);
                MMA_BF16(oacc[dp * 2], ph, u0, u1);
                MMA_BF16(oacc[dp * 2], pl, t0, t1);
                MMA_BF16(oacc[dp * 2 + 1], ph, t2, t3);
                MMA_BF16(oacc[dp * 2 + 1], ph, u2, u3);
                MMA_BF16(oacc[dp * 2 + 1], pl, t2, t3);
            }
        }

        if (jt + 2 < ntiles) {
            int ps = stage + 2; if (ps >= 3) ps -= 3;
            prefetch_kv(jt + 2, ps);
        }
        CP_COMMIT();
        if (++stage == 3) stage = 0;
    }

    const float inv1 = 1.f / l1;
    const float inv2 = 1.f / l2;
    const int r1 = m0 + wid * 16 + (lane >> 2);
    const int r2 = r1 + 8;
    const int cbase = h * DH + (lane & 3) * 2;
#pragma unroll
    for (int j = 0; j < 8; j++) {
        const int cc = cbase + j * 8;
        uint32_t hp, lp;
        split_pack(oacc[j][0] * inv1, oacc[j][1] * inv1, hp, lp);
        *reinterpret_cast<uint32_t*>(Ohi + ((size_t)b * L + r1) * D + cc) = hp;
        *reinterpret_cast<uint32_t*>(Olo + ((size_t)b * L + r1) * D + cc) = lp;
        split_pack(oacc[j][2] * inv2, oacc[j][3] * inv2, hp, lp);
        *reinterpret_cast<uint32_t*>(Ohi + ((size_t)b * L + r2) * D + cc) = hp;
        *reinterpret_cast<uint32_t*>(Olo + ((size_t)b * L + r2) * D + cc) = lp;
    }
}

// ---------------------------------------------------------------------------
// Launch
// ---------------------------------------------------------------------------
extern "C" void kernel_launch(void* const* d_in, const int* in_sizes, int n_in,
                              void* d_out, int out_size)
{
    const float* q_in = (const float*)d_in[0];
    const float* k_in = (const float*)d_in[1];
    const float* v_in = (const float*)d_in[2];
    const float* Wq   = (const float*)d_in[3];
    const float* Wk   = (const float*)d_in[4];
    const float* Wv   = (const float*)d_in[5];
    const float* Wo   = (const float*)d_in[6];
    float* out = (float*)d_out;

    __nv_bfloat16 *ainh, *ainl, *binh, *binl, *cinh, *cinl;
    __nv_bfloat16 *wqh, *wql, *wkh, *wkl, *wvh, *wvl, *woh, *wol;
    __nv_bfloat16 *qh, *qlp, *kh, *kl, *vh, *vl, *oh, *ol;
    cudaGetSymbolAddress((void**)&ainh, g_ain_hi);
    cudaGetSymbolAddress((void**)&ainl, g_ain_lo);
    cudaGetSymbolAddress((void**)&binh, g_bin_hi);
    cudaGetSymbolAddress((void**)&binl, g_bin_lo);
    cudaGetSymbolAddress((void**)&cinh, g_cin_hi);
    cudaGetSymbolAddress((void**)&cinl, g_cin_lo);
    cudaGetSymbolAddress((void**)&wqh, g_wq_hi);
    cudaGetSymbolAddress((void**)&wql, g_wq_lo);
    cudaGetSymbolAddress((void**)&wkh, g_wk_hi);
    cudaGetSymbolAddress((void**)&wkl, g_wk_lo);
    cudaGetSymbolAddress((void**)&wvh, g_wv_hi);
    cudaGetSymbolAddress((void**)&wvl, g_wv_lo);
    cudaGetSymbolAddress((void**)&woh, g_wo_hi);
    cudaGetSymbolAddress((void**)&wol, g_wo_lo);
    cudaGetSymbolAddress((void**)&qh, g_q_hi);
    cudaGetSymbolAddress((void**)&qlp, g_q_lo);
    cudaGetSymbolAddress((void**)&kh, g_k_hi);
    cudaGetSymbolAddress((void**)&kl, g_k_lo);
    cudaGetSymbolAddress((void**)&vh, g_v_hi);
    cudaGetSymbolAddress((void**)&vl, g_v_lo);
    cudaGetSymbolAddress((void**)&oh, g_o_hi);
    cudaGetSymbolAddress((void**)&ol, g_o_lo);

    cudaFuncSetAttribute(gemm_mma_kernel<true>,
                         cudaFuncAttributeMaxDynamicSharedMemorySize, GEMM_SMEM);
    cudaFuncSetAttribute(gemm_mma_kernel<false>,
                         cudaFuncAttributeMaxDynamicSharedMemorySize, GEMM_SMEM);
    cudaFuncSetAttribute(attn_mma_kernel,
                         cudaFuncAttributeMaxDynamicSharedMemorySize, ATTN_SMEM);

    const int Nrows = B * L;
    const int nInp4 = Nrows * D / 4;
    const int nW4   = D * D / 4;

    dim3 wgrid((nW4 + 255) / 256, 4);
    split_w4_kernel<<<wgrid, 256>>>(Wq, Wk, Wv, Wo);
    dim3 igrid((nInp4 + 255) / 256, 3);
    split_in3_kernel<<<igrid, 256>>>(q_in, k_in, v_in);

    dim3 ggrid(D / 256, Nrows / 128);   // (4, 64) = 256 CTAs
    const float qscale = 0.125f * 1.4426950408889634f;
    gemm_mma_kernel<true><<<ggrid, 256, GEMM_SMEM>>>(ainh, ainl, wqh, wql,
                                                     nullptr, qh, qlp, qscale);
    gemm_mma_kernel<true><<<ggrid, 256, GEMM_SMEM>>>(binh, binl, wkh, wkl,
                                                     nullptr, kh, kl, 1.f);
    gemm_mma_kernel<true><<<ggrid, 256, GEMM_SMEM>>>(cinh, cinl, wvh, wvl,
                                                     nullptr, vh, vl, 1.f);

    dim3 agrid(L / 128, B * H);
    attn_mma_kernel<<<agrid, 256, ATTN_SMEM>>>(qh, qlp, kh, kl, vh, vl, oh, ol);

    gemm_mma_kernel<false><<<ggrid, 256, GEMM_SMEM>>>(oh, ol, woh, wol,
                                                      out, nullptr, nullptr, 1.f);
}